// round 13
// baseline (speedup 1.0000x reference)
#include <cuda_runtime.h>
#include <cstdint>

#define VOCAB    100000
#define VOCABPAD 100096
#define DDIM     128
#define KDIM     256
#define NT_PF    448                    // 9 prod + 4 epi + 1 mma warps
#define NT_TREE  256
#define NPROD    288
#define TILE_M   128
#define NSTAGE   3

#define BLKB     131072u
#define CHB      32768u

// arena regions (bytes)
#define SCR_BASE  67108864u
#define SCR_STRIDE 524288u
#define A5OFF     262144u
#define FIN_BASE  134217728u
#define FIN2_BASE 134742016u

#if !defined(__CUDA_ARCH__) || defined(__CUDA_ARCH_FEAT_SM103_ALL) || \
    (defined(__CUDA_ARCH_SPECIFIC__) && (__CUDA_ARCH_SPECIFIC__ == 1030))
#define HAS_TCGEN05 1
#else
#define HAS_TCGEN05 0
#endif

// ---- SMEM frame ----
#define SM_B     0
#define SM_BLO   65536
#define SM_A     131072
#define SM_HDR   229376
#define SM_TMEMP (SM_HDR + 0)
#define SM_FULL(s)  (SM_HDR + 16 + (s) * 8)
#define SM_EMPTY(s) (SM_HDR + 48 + (s) * 8)
#define SM_EPI(p)   (SM_HDR + 80 + (p) * 8)
#define SM_EPID(p)  (SM_HDR + 96 + (p) * 8)
#define SM_BIAS  (SM_HDR + 128)
#define DYN_SMEM 231424

#define IDESC_N128 0x8200490u
#define IDESC_N256 0x8400490u

__device__ uint4 g_tree[8650752];
__device__ int   g_flags[1024];
// pre-split bf16 tables: row = 128 bf16 = 256B = 16 uint4
__device__ uint4 g_ELh[VOCABPAD * 16];
__device__ uint4 g_ELl[VOCABPAD * 16];
__device__ uint4 g_ERh[VOCABPAD * 16];
__device__ uint4 g_ERl[VOCABPAD * 16];

// ---------------- PTX helpers ----------------
__device__ __forceinline__ uint32_t smem_u32(const void* p) {
    uint32_t a;
    asm("{ .reg .u64 t; cvta.to.shared.u64 t, %1; cvt.u32.u64 %0, t; }" : "=r"(a) : "l"(p));
    return a;
}
__device__ __forceinline__ bool elect_one() {
    uint32_t pred;
    asm volatile("{ .reg .pred p; elect.sync _|p, 0xFFFFFFFF; selp.b32 %0, 1, 0, p; }" : "=r"(pred));
    return pred != 0;
}
__device__ __forceinline__ void sts128(uint32_t a, uint32_t x, uint32_t y, uint32_t z, uint32_t w) {
    asm volatile("st.shared.v4.b32 [%0], {%1,%2,%3,%4};" :: "r"(a), "r"(x), "r"(y), "r"(z), "r"(w) : "memory");
}
__device__ __forceinline__ int lds_s32(uint32_t a) {
    int v; asm volatile("ld.shared.b32 %0, [%1];" : "=r"(v) : "r"(a)); return v;
}
__device__ __forceinline__ float4 lds_f32x4(uint32_t a) {
    float4 v;
    asm volatile("ld.shared.v4.f32 {%0,%1,%2,%3}, [%4];"
                 : "=f"(v.x), "=f"(v.y), "=f"(v.z), "=f"(v.w) : "r"(a));
    return v;
}
__device__ __forceinline__ void sts_b32(uint32_t a, uint32_t v) {
    asm volatile("st.shared.b32 [%0], %1;" :: "r"(a), "r"(v) : "memory");
}
__device__ __forceinline__ void mbar_init(uint32_t a, uint32_t c) {
    asm volatile("mbarrier.init.shared.b64 [%0], %1;" :: "r"(a), "r"(c) : "memory");
}
__device__ __forceinline__ void mbar_arrive(uint32_t a) {
    asm volatile("mbarrier.arrive.shared.b64 _, [%0];" :: "r"(a) : "memory");
}
__device__ __forceinline__ void mbar_expect_tx(uint32_t a, uint32_t bytes) {
    asm volatile("mbarrier.arrive.expect_tx.shared.b64 _, [%0], %1;" :: "r"(a), "r"(bytes) : "memory");
}
__device__ __forceinline__ void bulk_g2s(uint32_t dst, const char* src, uint32_t bytes, uint32_t mbar) {
    asm volatile("cp.async.bulk.shared::cluster.global.mbarrier::complete_tx::bytes [%0], [%1], %2, [%3];"
                 :: "r"(dst), "l"(src), "r"(bytes), "r"(mbar) : "memory");
}
__device__ __forceinline__ void fence_proxy_async_s() {
    asm volatile("fence.proxy.async.shared::cta;" ::: "memory");
}
__device__ __forceinline__ void fence_proxy_async_g() {
    asm volatile("fence.proxy.async;" ::: "memory");
}
__device__ __forceinline__ int ld_acq(const int* p) {
    int v; asm volatile("ld.acquire.gpu.global.b32 %0, [%1];" : "=r"(v) : "l"(p) : "memory");
    return v;
}
__device__ __forceinline__ void red_rel_add1(int* p) {
    asm volatile("red.release.gpu.global.add.s32 [%0], 1;" :: "l"(p) : "memory");
}
__device__ __forceinline__ void nsleep() { asm volatile("nanosleep.u32 64;" ::: ); }

#if HAS_TCGEN05
__device__ __forceinline__ void mbar_wait(uint32_t a, uint32_t parity) {
    asm volatile(
        "{\n\t.reg .pred P;\n\t"
        "W%=:\n\t"
        "mbarrier.try_wait.parity.acquire.cta.shared::cta.b64 P, [%0], %1, 0x989680;\n\t"
        "@P bra.uni D%=;\n\t"
        "bra.uni W%=;\n\t"
        "D%=:\n\t}"
        :: "r"(a), "r"(parity) : "memory");
}
__device__ __forceinline__ void tmem_alloc(uint32_t dst, uint32_t n) {
    asm volatile("tcgen05.alloc.cta_group::1.sync.aligned.shared::cta.b32 [%0], %1;"
                 :: "r"(dst), "r"(n) : "memory");
}
__device__ __forceinline__ void tmem_relinquish() {
    asm volatile("tcgen05.relinquish_alloc_permit.cta_group::1.sync.aligned;");
}
__device__ __forceinline__ void tmem_dealloc(uint32_t t, uint32_t n) {
    asm volatile("tcgen05.dealloc.cta_group::1.sync.aligned.b32 %0, %1;" :: "r"(t), "r"(n));
}
__device__ __forceinline__ void mma_f16_ss(uint32_t d, uint64_t ad, uint64_t bd, uint32_t idesc, uint32_t en) {
    asm volatile(
        "{\n\t.reg .pred p;\n\tsetp.ne.u32 p, %4, 0;\n\t"
        "tcgen05.mma.cta_group::1.kind::f16 [%0], %1, %2, %3, {%5,%5,%5,%5}, p;\n\t}"
        :: "r"(d), "l"(ad), "l"(bd), "r"(idesc), "r"(en), "r"(0u) : "memory");
}
__device__ __forceinline__ void mma_commit(uint32_t mbar) {
    asm volatile("tcgen05.commit.cta_group::1.mbarrier::arrive::one.shared::cluster.b64 [%0];"
                 :: "r"(mbar) : "memory");
}
__device__ __forceinline__ void fence_after()  { asm volatile("tcgen05.fence::after_thread_sync;"  ::: "memory"); }
__device__ __forceinline__ void fence_before() { asm volatile("tcgen05.fence::before_thread_sync;" ::: "memory"); }
__device__ __forceinline__ void wait_ld()      { asm volatile("tcgen05.wait::ld.sync.aligned;"     ::: "memory"); }
__device__ __forceinline__ void ldtm32(uint32_t* r, uint32_t ta) {
    asm volatile(
        "tcgen05.ld.sync.aligned.32x32b.x32.b32 "
        "{%0, %1, %2, %3, %4, %5, %6, %7, "
        " %8, %9, %10, %11, %12, %13, %14, %15, "
        " %16, %17, %18, %19, %20, %21, %22, %23, "
        " %24, %25, %26, %27, %28, %29, %30, %31}, [%32];"
        : "=r"(r[0]), "=r"(r[1]), "=r"(r[2]), "=r"(r[3]),
          "=r"(r[4]), "=r"(r[5]), "=r"(r[6]), "=r"(r[7]),
          "=r"(r[8]), "=r"(r[9]), "=r"(r[10]), "=r"(r[11]),
          "=r"(r[12]), "=r"(r[13]), "=r"(r[14]), "=r"(r[15]),
          "=r"(r[16]), "=r"(r[17]), "=r"(r[18]), "=r"(r[19]),
          "=r"(r[20]), "=r"(r[21]), "=r"(r[22]), "=r"(r[23]),
          "=r"(r[24]), "=r"(r[25]), "=r"(r[26]), "=r"(r[27]),
          "=r"(r[28]), "=r"(r[29]), "=r"(r[30]), "=r"(r[31])
        : "r"(ta));
}
#endif // HAS_TCGEN05

__device__ __forceinline__ uint32_t swz(uint32_t off) { return off ^ ((off >> 3) & 0x70); }

__device__ __forceinline__ uint64_t mk_desc(uint32_t addr) {
    const uint64_t base = (uint64_t(2) << 61) | (uint64_t(1) << 46) |
                          (uint64_t(64) << 32) | (uint64_t(1) << 16);
    return base | ((uint64_t)(addr >> 4) & 0x3FFF);
}

// split 8 fp32 -> bf16 hi + exact-residual bf16 lo
__device__ __forceinline__ void split8(const float4& v0, const float4& v1, uint4& h, uint4& l) {
    float f[8] = {v0.x, v0.y, v0.z, v0.w, v1.x, v1.y, v1.z, v1.w};
    uint32_t hh[4], ll[4];
#pragma unroll
    for (int q = 0; q < 4; q++) {
        float a = f[2 * q], b = f[2 * q + 1];
        uint32_t hv;
        asm("cvt.rn.bf16x2.f32 %0, %1, %2;" : "=r"(hv) : "f"(b), "f"(a));
        hh[q] = hv;
        float ha = __uint_as_float(hv << 16);
        float hb = __uint_as_float(hv & 0xFFFF0000u);
        asm("cvt.rn.bf16x2.f32 %0, %1, %2;" : "=r"(ll[q]) : "f"(b - hb), "f"(a - ha));
    }
    h = make_uint4(hh[0], hh[1], hh[2], hh[3]);
    l = make_uint4(ll[0], ll[1], ll[2], ll[3]);
}

#if HAS_TCGEN05
// 12 split-MMAs for one K=64 chunk (A in ring stage s, B chunk c)
__device__ __forceinline__ void mma_chunk(uint32_t dA, uint32_t sb, int s, int c, bool first) {
    const uint32_t aHi = sb + SM_A + s * 32768;
    const uint64_t adh = mk_desc(aHi), adl = mk_desc(aHi + 16384);
    const uint64_t bdh = mk_desc(sb + SM_B + c * 16384);
    const uint64_t bdl = mk_desc(sb + SM_BLO + c * 16384);
#pragma unroll
    for (int ks = 0; ks < 4; ks++)
        mma_f16_ss(dA, adh + 2 * ks, bdh + 2 * ks, IDESC_N128, (!first || ks > 0) ? 1u : 0u);
#pragma unroll
    for (int ks = 0; ks < 4; ks++)
        mma_f16_ss(dA, adh + 2 * ks, bdl + 2 * ks, IDESC_N128, 1u);
#pragma unroll
    for (int ks = 0; ks < 4; ks++)
        mma_f16_ss(dA, adl + 2 * ks, bdh + 2 * ks, IDESC_N128, 1u);
}

// direct-SMEM compact A block at sb+SM_A
__device__ __forceinline__ void mma_chunk_direct(uint32_t dA, uint32_t sb, uint32_t half, int c, bool first) {
    const uint32_t b0 = sb + SM_A + (uint32_t)c * 2u * half;
    const uint64_t adh = mk_desc(b0), adl = mk_desc(b0 + half);
    const uint64_t bdh = mk_desc(sb + SM_B + c * 16384);
    const uint64_t bdl = mk_desc(sb + SM_BLO + c * 16384);
#pragma unroll
    for (int ks = 0; ks < 4; ks++)
        mma_f16_ss(dA, adh + 2 * ks, bdh + 2 * ks, IDESC_N128, (!first || ks > 0) ? 1u : 0u);
#pragma unroll
    for (int ks = 0; ks < 4; ks++)
        mma_f16_ss(dA, adh + 2 * ks, bdl + 2 * ks, IDESC_N128, 1u);
#pragma unroll
    for (int ks = 0; ks < 4; ks++)
        mma_f16_ss(dA, adl + 2 * ks, bdh + 2 * ks, IDESC_N128, 1u);
}

// fused12 epilogue: fixed 128-row consumer blocks (GMEM)
__device__ __forceinline__ void epi_store_chunked(uint32_t sb, uint32_t tmem, int p,
                                                  int tau, char* consBase, int q) {
    char* blkBase = consBase + (size_t)(tau >> 1) * BLKB;
    const int il = 64 * (tau & 1) + (q >> 1);
    const int cpar = 2 * (q & 1);
#pragma unroll
    for (int qq = 0; qq < 4; qq++) {
        uint32_t d[32];
        ldtm32(d, tmem + p * 128 + qq * 32);
        wait_ld();
        char* cb = blkBase + (size_t)(cpar + (qq >> 1)) * CHB;
#pragma unroll
        for (int u = 0; u < 4; u++) {
            float4 bv0 = lds_f32x4(sb + SM_BIAS + (qq * 32 + u * 8) * 4);
            float4 bv1 = lds_f32x4(sb + SM_BIAS + (qq * 32 + u * 8 + 4) * 4);
            float4 v0, v1;
            v0.x = __uint_as_float(d[8*u+0]) + bv0.x; v0.y = __uint_as_float(d[8*u+1]) + bv0.y;
            v0.z = __uint_as_float(d[8*u+2]) + bv0.z; v0.w = __uint_as_float(d[8*u+3]) + bv0.w;
            v1.x = __uint_as_float(d[8*u+4]) + bv1.x; v1.y = __uint_as_float(d[8*u+5]) + bv1.y;
            v1.z = __uint_as_float(d[8*u+6]) + bv1.z; v1.w = __uint_as_float(d[8*u+7]) + bv1.w;
            uint4 h, l; split8(v0, v1, h, l);
            const uint32_t off = swz((uint32_t)il * 128 + (32 * (qq & 1) + 8 * u) * 2);
            *(uint4*)(cb + off) = h;
            *(uint4*)(cb + 16384 + off) = l;
        }
    }
}

// generalized epilogue store to GMEM block (whole-warp skip when slice invalid)
__device__ __forceinline__ void epi_store2(uint32_t sb, uint32_t tmem, int p, int V,
                                           char* dst, uint32_t dArB, int ilBase, int q) {
    if ((q & ~31) >= V) return;
    const uint32_t chbd = 2 * dArB;
#pragma unroll
    for (int qq = 0; qq < 4; qq++) {
        uint32_t d[32];
        ldtm32(d, tmem + p * 128 + qq * 32);
        wait_ld();
        if (q < V) {
            const int il = ilBase + (q >> 1);
            char* cb = dst + (size_t)(2 * (q & 1) + (qq >> 1)) * chbd;
#pragma unroll
            for (int u = 0; u < 4; u++) {
                float4 bv0 = lds_f32x4(sb + SM_BIAS + (qq * 32 + u * 8) * 4);
                float4 bv1 = lds_f32x4(sb + SM_BIAS + (qq * 32 + u * 8 + 4) * 4);
                float4 v0, v1;
                v0.x = __uint_as_float(d[8*u+0]) + bv0.x; v0.y = __uint_as_float(d[8*u+1]) + bv0.y;
                v0.z = __uint_as_float(d[8*u+2]) + bv0.z; v0.w = __uint_as_float(d[8*u+3]) + bv0.w;
                v1.x = __uint_as_float(d[8*u+4]) + bv1.x; v1.y = __uint_as_float(d[8*u+5]) + bv1.y;
                v1.z = __uint_as_float(d[8*u+6]) + bv1.z; v1.w = __uint_as_float(d[8*u+7]) + bv1.w;
                uint4 h, l; split8(v0, v1, h, l);
                const uint32_t off = swz((uint32_t)il * 128 + (32 * (qq & 1) + 8 * u) * 2);
                *(uint4*)(cb + off) = h;
                *(uint4*)(cb + dArB + off) = l;
            }
        }
    }
}

// epilogue store into SMEM compact block (whole-warp skip when slice invalid)
__device__ __forceinline__ void epi_store2_smem(uint32_t sb, uint32_t tmem, int p, int V,
                                                uint32_t dstBase, uint32_t dArB, int q) {
    if ((q & ~31) >= V) return;
    const uint32_t chbd = 2 * dArB;
#pragma unroll
    for (int qq = 0; qq < 4; qq++) {
        uint32_t d[32];
        ldtm32(d, tmem + p * 128 + qq * 32);
        wait_ld();
        if (q < V) {
            const int il = q >> 1;
            uint32_t cb = dstBase + (uint32_t)(2 * (q & 1) + (qq >> 1)) * chbd;
#pragma unroll
            for (int u = 0; u < 4; u++) {
                float4 bv0 = lds_f32x4(sb + SM_BIAS + (qq * 32 + u * 8) * 4);
                float4 bv1 = lds_f32x4(sb + SM_BIAS + (qq * 32 + u * 8 + 4) * 4);
                float4 v0, v1;
                v0.x = __uint_as_float(d[8*u+0]) + bv0.x; v0.y = __uint_as_float(d[8*u+1]) + bv0.y;
                v0.z = __uint_as_float(d[8*u+2]) + bv0.z; v0.w = __uint_as_float(d[8*u+3]) + bv0.w;
                v1.x = __uint_as_float(d[8*u+4]) + bv1.x; v1.y = __uint_as_float(d[8*u+5]) + bv1.y;
                v1.z = __uint_as_float(d[8*u+6]) + bv1.z; v1.w = __uint_as_float(d[8*u+7]) + bv1.w;
                uint4 h, l; split8(v0, v1, h, l);
                const uint32_t off = swz((uint32_t)il * 128 + (32 * (qq & 1) + 8 * u) * 2);
                sts128(cb + off, h.x, h.y, h.z, h.w);
                sts128(cb + dArB + off, l.x, l.y, l.z, l.w);
            }
        }
    }
}
#endif

// ---------------------------------------------------------------------------
__global__ void clear_flags_k() {
    int i = blockIdx.x * 256 + threadIdx.x;
    if (i < 1024) g_flags[i] = 0;
}

// ---------------------------------------------------------------------------
// Precompute: EL/ER, output PRE-SPLIT bf16 hi/lo tables (row = 16 uint4).
// ---------------------------------------------------------------------------
__global__ __launch_bounds__(NT_PF, 1)
void precompute_tc(const float* __restrict__ emb, const float* __restrict__ W,
                   uint4* __restrict__ ELh, uint4* __restrict__ ELl,
                   uint4* __restrict__ ERh, uint4* __restrict__ ERl, int numTiles)
{
#if HAS_TCGEN05
    extern __shared__ char dsm[];
    const uint32_t sb = (smem_u32(dsm) + 1023) & ~1023u;
    const int tid = threadIdx.x, wid = tid >> 5, lid = tid & 31;

    if (tid == 0) {
#pragma unroll
        for (int s = 0; s < NSTAGE; s++) { mbar_init(SM_FULL(s) + sb, NPROD); mbar_init(SM_EMPTY(s) + sb, 1); }
#pragma unroll
        for (int p = 0; p < 2; p++) { mbar_init(SM_EPI(p) + sb, 1); mbar_init(SM_EPID(p) + sb, 128); }
    }
    if (tid < 256) {
        const int n = tid;
        const float* wrow = W + (size_t)(n & 127) * KDIM + (n >> 7) * 128;
#pragma unroll
        for (int g = 0; g < 16; g++) {
            int k0 = g * 8;
            float4 v0 = *(const float4*)(wrow + k0);
            float4 v1 = *(const float4*)(wrow + k0 + 4);
            uint4 h, l; split8(v0, v1, h, l);
            uint32_t off = (k0 >> 6) * 32768 + swz(n * 128 + (k0 & 63) * 2);
            sts128(sb + SM_B + off, h.x, h.y, h.z, h.w);
            sts128(sb + SM_BLO + off, l.x, l.y, l.z, l.w);
        }
    }
    fence_proxy_async_s();
    __syncthreads();
    if (wid == 0) { tmem_alloc(sb + SM_TMEMP, 512); tmem_relinquish(); }
    __syncthreads();
    const uint32_t tmem = (uint32_t)lds_s32(sb + SM_TMEMP);

    const bool mmaLead = (wid == 13) && elect_one();
    int uc[NSTAGE] = {0, 0, 0}, fc[NSTAGE] = {0, 0, 0}, tp[2] = {0, 0}, epc[2] = {0, 0};
    int tl = 0, prevRow = 0;

    for (int tile = blockIdx.x; tile < numTiles; tile += gridDim.x) {
        const int tileRow = tile * TILE_M;
        if (tid < NPROD) {
#pragma unroll
            for (int c = 0; c < 2; c++) {
                const int s = (tl * 2 + c) % NSTAGE;
                const uint32_t hiB = sb + SM_A + s * 32768, loB = hiB + 16384;

                int i0 = tid;
                int er0 = tileRow + (i0 >> 3); if (er0 > VOCAB - 1) er0 = VOCAB - 1;
                const float* s0 = emb + (size_t)er0 * DDIM + c * 64 + (i0 & 7) * 8;
                float4 v0 = *(const float4*)s0;
                float4 v1 = *(const float4*)(s0 + 4);
                int i1 = i0 + NPROD;

                if (uc[s] > 0) mbar_wait(sb + SM_EMPTY(s), (uc[s] - 1) & 1);
                uc[s]++;

                while (true) {
                    float4 nv0, nv1;
                    if (i1 < 1024) {
                        int er1 = tileRow + (i1 >> 3); if (er1 > VOCAB - 1) er1 = VOCAB - 1;
                        const float* s1 = emb + (size_t)er1 * DDIM + c * 64 + (i1 & 7) * 8;
                        nv0 = *(const float4*)s1;
                        nv1 = *(const float4*)(s1 + 4);
                    }
                    uint4 h, l; split8(v0, v1, h, l);
                    const uint32_t off = swz((i0 >> 3) * 128 + (i0 & 7) * 16);
                    sts128(hiB + off, h.x, h.y, h.z, h.w);
                    sts128(loB + off, l.x, l.y, l.z, l.w);
                    if (i1 >= 1024) break;
                    i0 = i1; v0 = nv0; v1 = nv1; i1 += NPROD;
                }
                fence_proxy_async_s();
                mbar_arrive(sb + SM_FULL(s));
            }
        } else if (mmaLead) {
            const int p = tl & 1;
            if (tp[p] > 0) mbar_wait(sb + SM_EPID(p), (tp[p] - 1) & 1);
            tp[p]++;
            const uint32_t dA = tmem + p * 256;
#pragma unroll
            for (int c = 0; c < 2; c++) {
                const int s = (tl * 2 + c) % NSTAGE;
                mbar_wait(sb + SM_FULL(s), fc[s] & 1); fc[s]++;
                const uint32_t aHi = sb + SM_A + s * 32768;
                const uint64_t adh = mk_desc(aHi), adl = mk_desc(aHi + 16384);
                const uint64_t bdh = mk_desc(sb + SM_B + c * 32768);
                const uint64_t bdl = mk_desc(sb + SM_BLO + c * 32768);
#pragma unroll
                for (int ks = 0; ks < 4; ks++)
                    mma_f16_ss(dA, adh + 2 * ks, bdh + 2 * ks, IDESC_N256, (c > 0 || ks > 0) ? 1u : 0u);
#pragma unroll
                for (int ks = 0; ks < 4; ks++)
                    mma_f16_ss(dA, adh + 2 * ks, bdl + 2 * ks, IDESC_N256, 1u);
#pragma unroll
                for (int ks = 0; ks < 4; ks++)
                    mma_f16_ss(dA, adl + 2 * ks, bdh + 2 * ks, IDESC_N256, 1u);
                mma_commit(sb + SM_EMPTY(s));
            }
            mma_commit(sb + SM_EPI(p));
        } else if (wid >= 9 && wid <= 12 && tl >= 1) {
            const int p = (tl - 1) & 1;
            mbar_wait(sb + SM_EPI(p), epc[p] & 1); epc[p]++;
            fence_after();
            const int rowg = prevRow + (wid & 3) * 32 + lid;
#pragma unroll
            for (int q = 0; q < 8; q++) {
                uint32_t d[32];
                ldtm32(d, tmem + p * 256 + q * 32);
                wait_ld();
                const int col0 = q * 32;
                uint4* th; uint4* tl2; int colT;
                if (col0 < 128) { th = ELh; tl2 = ELl; colT = col0; }
                else            { th = ERh; tl2 = ERl; colT = col0 - 128; }
#pragma unroll
                for (int u = 0; u < 4; u++) {
                    float4 v0 = make_float4(__uint_as_float(d[8*u+0]), __uint_as_float(d[8*u+1]),
                                            __uint_as_float(d[8*u+2]), __uint_as_float(d[8*u+3]));
                    float4 v1 = make_float4(__uint_as_float(d[8*u+4]), __uint_as_float(d[8*u+5]),
                                            __uint_as_float(d[8*u+6]), __uint_as_float(d[8*u+7]));
                    uint4 h, l; split8(v0, v1, h, l);
                    th[(size_t)rowg * 16 + (colT >> 3) + u]  = h;
                    tl2[(size_t)rowg * 16 + (colT >> 3) + u] = l;
                }
            }
            fence_before();
            mbar_arrive(sb + SM_EPID(p));
        }
        prevRow = tileRow; tl++;
    }

    if (wid >= 9 && wid <= 12 && tl >= 1) {
        const int p = (tl - 1) & 1;
        mbar_wait(sb + SM_EPI(p), epc[p] & 1); epc[p]++;
        fence_after();
        const int rowg = prevRow + (wid & 3) * 32 + lid;
#pragma unroll
        for (int q = 0; q < 8; q++) {
            uint32_t d[32];
            ldtm32(d, tmem + p * 256 + q * 32);
            wait_ld();
            const int col0 = q * 32;
            uint4* th; uint4* tl2; int colT;
            if (col0 < 128) { th = ELh; tl2 = ELl; colT = col0; }
            else            { th = ERh; tl2 = ERl; colT = col0 - 128; }
#pragma unroll
            for (int u = 0; u < 4; u++) {
                float4 v0 = make_float4(__uint_as_float(d[8*u+0]), __uint_as_float(d[8*u+1]),
                                        __uint_as_float(d[8*u+2]), __uint_as_float(d[8*u+3]));
                float4 v1 = make_float4(__uint_as_float(d[8*u+4]), __uint_as_float(d[8*u+5]),
                                        __uint_as_float(d[8*u+6]), __uint_as_float(d[8*u+7]));
                uint4 h, l; split8(v0, v1, h, l);
                th[(size_t)rowg * 16 + (colT >> 3) + u]  = h;
                tl2[(size_t)rowg * 16 + (colT >> 3) + u] = l;
            }
        }
        fence_before();
    }
    __syncthreads();
    if (wid == 0) tmem_dealloc(tmem, 512);
#else
    (void)emb; (void)W; (void)ELh; (void)ELl; (void)ERh; (void)ERl; (void)numTiles;
#endif
}

// ---------------------------------------------------------------------------
// Fused levels 1+2 as ONE K=512 GEMM: A-row m = [EL[i0]|ER[i1]|EL[i2]|ER[i3]]
// (pure bf16 copy from pre-split tables), B chunks reused {0,1,0,1,2,3,2,3},
// bias' = W.[b;b]+b added in epilogue.
// ---------------------------------------------------------------------------
__global__ __launch_bounds__(NT_PF, 1)
void fused12_tc(const int* __restrict__ ids,
                const uint4* __restrict__ ELh, const uint4* __restrict__ ELl,
                const uint4* __restrict__ ERh, const uint4* __restrict__ ERl,
                const float* __restrict__ W, const float* __restrict__ bias, int numTiles)
{
#if HAS_TCGEN05
    extern __shared__ char dsm[];
    const uint32_t sb = (smem_u32(dsm) + 1023) & ~1023u;
    const int tid = threadIdx.x, wid = tid >> 5, lid = tid & 31;
    char* arena = (char*)g_tree;

    if (tid == 0) {
#pragma unroll
        for (int s = 0; s < NSTAGE; s++) { mbar_init(SM_FULL(s) + sb, NPROD); mbar_init(SM_EMPTY(s) + sb, 1); }
#pragma unroll
        for (int p = 0; p < 2; p++) { mbar_init(SM_EPI(p) + sb, 1); mbar_init(SM_EPID(p) + sb, 128); }
    }
    // bias' = b + W.[b;b]
    if (tid < 128) {
        float s = bias[tid];
        const float* wr = W + (size_t)tid * KDIM;
        for (int k = 0; k < 256; k++) s += wr[k] * bias[k & 127];
        sts_b32(sb + SM_BIAS + tid * 4, __float_as_uint(s));
    }

    if (tid < 256) {
        const int n = tid >> 1, h2 = tid & 1;
#pragma unroll
        for (int g = 0; g < 16; g++) {
            int k0 = h2 * 128 + g * 8;
            float4 v0 = *(const float4*)(W + (size_t)n * KDIM + k0);
            float4 v1 = *(const float4*)(W + (size_t)n * KDIM + k0 + 4);
            uint4 h, l; split8(v0, v1, h, l);
            uint32_t off = (k0 >> 6) * 16384 + swz(n * 128 + (k0 & 63) * 2);
            sts128(sb + SM_B + off, h.x, h.y, h.z, h.w);
            sts128(sb + SM_BLO + off, l.x, l.y, l.z, l.w);
        }
    }
    fence_proxy_async_s();
    __syncthreads();
    if (wid == 0) { tmem_alloc(sb + SM_TMEMP, 256); tmem_relinquish(); }
    __syncthreads();
    const uint32_t tmem = (uint32_t)lds_s32(sb + SM_TMEMP);

    const bool mmaLead = (wid == 13) && elect_one();
    int uc[NSTAGE] = {0, 0, 0}, fc[NSTAGE] = {0, 0, 0}, tp[2] = {0, 0}, epc[2] = {0, 0};
    int tl = 0, prevTile = 0;

    for (int tile = blockIdx.x; tile < numTiles; tile += gridDim.x) {
        const int tileRow = tile * TILE_M;
        if (tid < NPROD) {
#pragma unroll
            for (int c = 0; c < 8; c++) {
                const int s = (tl * 8 + c) % NSTAGE;
                const uint32_t hiB = sb + SM_A + s * 32768, loB = hiB + 16384;
                const int p4 = c >> 1;
                const uint4* Th = (p4 & 1) ? ERh : ELh;
                const uint4* Tl = (p4 & 1) ? ERl : ELl;
                const int halfSel = (c & 1) * 8;

                // 2-deep pipelined pure-copy gather (issued before EMPTY wait)
                int i0 = tid;
                int id0 = ids[4 * (tileRow + (i0 >> 3)) + p4];
                uint4 h0 = Th[(size_t)id0 * 16 + halfSel + (i0 & 7)];
                uint4 g0 = Tl[(size_t)id0 * 16 + halfSel + (i0 & 7)];
                int i1 = i0 + NPROD;
                int id1;
                if (i1 < 1024) id1 = ids[4 * (tileRow + (i1 >> 3)) + p4];

                if (uc[s] > 0) mbar_wait(sb + SM_EMPTY(s), (uc[s] - 1) & 1);
                uc[s]++;

                while (true) {
                    uint4 h1, g1;
                    if (i1 < 1024) {
                        h1 = Th[(size_t)id1 * 16 + halfSel + (i1 & 7)];
                        g1 = Tl[(size_t)id1 * 16 + halfSel + (i1 & 7)];
                    }
                    int i2 = i1 + NPROD;
                    int id2;
                    if (i2 < 1024) id2 = ids[4 * (tileRow + (i2 >> 3)) + p4];

                    const uint32_t off = swz((i0 >> 3) * 128 + (i0 & 7) * 16);
                    sts128(hiB + off, h0.x, h0.y, h0.z, h0.w);
                    sts128(loB + off, g0.x, g0.y, g0.z, g0.w);
                    if (i1 >= 1024) break;
                    i0 = i1; h0 = h1; g0 = g1; id1 = id2; i1 = i2;
                }
                fence_proxy_async_s();
                mbar_arrive(sb + SM_FULL(s));
            }
        } else if (mmaLead) {
            const int p = tl & 1;
            if (tp[p] > 0) mbar_wait(sb + SM_EPID(p), (tp[p] - 1) & 1);
            tp[p]++;
            const uint32_t dA = tmem + p * 128;
            const int bmap[8] = {0, 1, 0, 1, 2, 3, 2, 3};
#pragma unroll
            for (int c = 0; c < 8; c++) {
                const int s = (tl * 8 + c) % NSTAGE;
                mbar_wait(sb + SM_FULL(s), fc[s] & 1); fc[s]++;
                mma_chunk(dA, sb, s, bmap[c], c == 0);
                mma_commit(sb + SM_EMPTY(s));
            }
            mma_commit(sb + SM_EPI(p));
        } else if (wid >= 9 && wid <= 12 && tl >= 1) {
            const int p = (tl - 1) & 1;
            mbar_wait(sb + SM_EPI(p), epc[p] & 1); epc[p]++;
            fence_after();
            epi_store_chunked(sb, tmem, p, prevTile, arena, (wid & 3) * 32 + lid);
            fence_before();
            fence_proxy_async_g();
            mbar_arrive(sb + SM_EPID(p));
        }
        prevTile = tile; tl++;
    }

    if (wid >= 9 && wid <= 12 && tl >= 1) {
        const int p = (tl - 1) & 1;
        mbar_wait(sb + SM_EPI(p), epc[p] & 1); epc[p]++;
        fence_after();
        epi_store_chunked(sb, tmem, p, prevTile, arena, (wid & 3) * 32 + lid);
        fence_before();
        fence_proxy_async_g();
    }
    __syncthreads();
    if (wid == 0) tmem_dealloc(tmem, 256);
#else
    (void)ids; (void)ELh; (void)ELl; (void)ERh; (void)ERl; (void)W; (void)bias; (void)numTiles;
#endif
}

// ---------------------------------------------------------------------------
// Tree kernel (unchanged from R12)
// ---------------------------------------------------------------------------
__global__ __launch_bounds__(NT_TREE, 1)
void tree2_tc(const float* __restrict__ W, const float* __restrict__ bias,
              float* __restrict__ out)
{
#if HAS_TCGEN05
    extern __shared__ char dsm[];
    const uint32_t sb = (smem_u32(dsm) + 1023) & ~1023u;
    const int tid = threadIdx.x, wid = tid >> 5, lid = tid & 31;
    const int bid = blockIdx.x;
    char* arena = (char*)g_tree;
    char* S    = arena + SCR_BASE + (size_t)bid * SCR_STRIDE;
    char* FIN  = arena + FIN_BASE;
    char* FIN2 = arena + FIN2_BASE;

    if (tid == 0) {
#pragma unroll
        for (int s = 0; s < NSTAGE; s++) { mbar_init(SM_FULL(s) + sb, 1); mbar_init(SM_EMPTY(s) + sb, 1); }
#pragma unroll
        for (int p = 0; p < 2; p++) { mbar_init(SM_EPI(p) + sb, 1); mbar_init(SM_EPID(p) + sb, 128); }
    }
    if (tid < 128) sts_b32(sb + SM_BIAS + tid * 4, __float_as_uint(bias[tid]));

    {
        const int n = tid >> 1, h2 = tid & 1;
#pragma unroll
        for (int g = 0; g < 16; g++) {
            int k0 = h2 * 128 + g * 8;
            float4 v0 = *(const float4*)(W + (size_t)n * KDIM + k0);
            float4 v1 = *(const float4*)(W + (size_t)n * KDIM + k0 + 4);
            uint4 h, l; split8(v0, v1, h, l);
            uint32_t off = (k0 >> 6) * 16384 + swz(n * 128 + (k0 & 63) * 2);
            sts128(sb + SM_B + off, h.x, h.y, h.z, h.w);
            sts128(sb + SM_BLO + off, l.x, l.y, l.z, l.w);
        }
    }
    fence_proxy_async_s();
    __syncthreads();
    if (wid == 0) { tmem_alloc(sb + SM_TMEMP, 256); tmem_relinquish(); }
    __syncthreads();
    const uint32_t tmem = (uint32_t)lds_s32(sb + SM_TMEMP);

    const int nG = 11 + (bid < 4 ? 1 : 0) + (bid < 2 ? 1 : 0);

    if (wid == 7 && elect_one()) {
        int kChunk = 0;
        int issued[NSTAGE] = {0, 0, 0}, fcons[NSTAGE] = {0, 0, 0};
        int epidW[2] = {0, 0};
        int epiSeen = -1;
        auto waitEpi = [&](int e) {
            while (epiSeen < e) {
                epiSeen++;
                const int pp = epiSeen & 1;
                mbar_wait(sb + SM_EPID(pp), epidW[pp] & 1);
                epidW[pp]++;
            }
        };
        auto issueChunk = [&](int k, const char* src, uint32_t half, int c) {
            const int s = k % NSTAGE;
            if (issued[s] > 0) mbar_wait(sb + SM_EMPTY(s), (issued[s] - 1) & 1);
            issued[s]++;
            mbar_expect_tx(sb + SM_FULL(s), 2 * half);
            bulk_g2s(sb + SM_A + s * 32768,         src + (size_t)c * 2 * half,        half, sb + SM_FULL(s));
            bulk_g2s(sb + SM_A + s * 32768 + 16384, src + (size_t)c * 2 * half + half, half, sb + SM_FULL(s));
        };

        for (int g = 0; g < nG; g++) {
            if (g == 2 || g == 3) waitEpi(g - 2);
            else if (g == 4) waitEpi(2);
            else if (g == 5) waitEpi(3);
            else if (g == 6) waitEpi(5);
            else if (g >= 7) waitEpi(g - 1);
            if (g == 11) { while (ld_acq(&g_flags[0]) < 16384) nsleep(); }
            if (g == 12) { while (ld_acq(&g_flags[1]) < 512)   nsleep(); }

            const int p = g & 1;
            const uint32_t dA = tmem + p * 128;

            if (g >= 7 && g <= 10) {
                const uint32_t half = (g == 7) ? 8192u : (g == 8) ? 4096u : (g == 9) ? 2048u : 1024u;
#pragma unroll
                for (int c = 0; c < 4; c++)
                    mma_chunk_direct(dA, sb, half, c, c == 0);
            } else {
                const char* src; uint32_t half = 16384;
                if (g < 4)       src = arena + (size_t)(4 * bid + g) * BLKB;
                else if (g == 4) src = S;
                else if (g == 5) src = S + BLKB;
                else if (g == 6) src = S + A5OFF;
                else if (g == 11) src = FIN + (size_t)bid * BLKB;
                else              src = FIN2 + (size_t)bid * BLKB;

                issueChunk(kChunk + 0, src, half, 0);
                issueChunk(kChunk + 1, src, half, 1);
                issueChunk(kChunk + 2, src, half, 2);
                { const int s = kChunk % NSTAGE;
                  mbar_wait(sb + SM_FULL(s), fcons[s] & 1); fcons[s]++;
                  mma_chunk(dA, sb, s, 0, true);
                  mma_commit(sb + SM_EMPTY(s)); }
                issueChunk(kChunk + 3, src, half, 3);
#pragma unroll
                for (int c = 1; c < 4; c++) {
                    const int s = (kChunk + c) % NSTAGE;
                    mbar_wait(sb + SM_FULL(s), fcons[s] & 1); fcons[s]++;
                    mma_chunk(dA, sb, s, c, false);
                    mma_commit(sb + SM_EMPTY(s));
                }
                kChunk += 4;
            }
            mma_commit(sb + SM_EPI(p));
        }
    } else if (wid < 4) {
        int epc[2] = {0, 0};
        const int q = wid * 32 + lid;
        for (int e = 0; e < nG; e++) {
            const int p = e & 1;
            mbar_wait(sb + SM_EPI(p), epc[p] & 1); epc[p]++;
            fence_after();
            if (e == 12) {
                float* op = out + (size_t)(128 * bid + q) * DDIM;
#pragma unroll
                for (int qq = 0; qq < 4; qq++) {
                    uint32_t d[32];
                    ldtm32(d, tmem + p * 128 + qq * 32);
                    wait_ld();
#pragma unroll
                    for (int u = 0; u < 8; u++) {
                        float4 bv = lds_f32x4(sb + SM_BIAS + (qq * 32 + u * 4) * 4);
                        *(float4*)(op + qq * 32 + u * 4) =
                            make_float4(__uint_as_float(d[4*u+0]) + bv.x, __uint_as_float(d[4*u+1]) + bv.y,
                                        __uint_as_float(d[4*u+2]) + bv.z, __uint_as_float(d[4*u+3]) + bv.w);
                    }
                }
                fence_before();
            } else if (e >= 6 && e <= 9) {
                const uint32_t dArB = (e == 6) ? 8192u : (e == 7) ? 4096u : (e == 8) ? 2048u : 1024u;
                const int V = (e == 6) ? 128 : (e == 7) ? 64 : (e == 8) ? 32 : 16;
                epi_store2_smem(sb, tmem, p, V, sb + SM_A, dArB, q);
                fence_before();
                fence_proxy_async_s();
            } else {
                int V, ilBase; char* dst; uint32_t dArB = 16384;
                if (e < 6)       { V = 128; dst = S + (size_t)(e >> 1) * BLKB; ilBase = 64 * (e & 1); }
                else if (e == 10){ V = 8;   dst = FIN + (size_t)(bid >> 5) * BLKB; ilBase = 4 * (bid & 31); }
                else             { V = 128; dst = FIN2 + (size_t)(bid >> 1) * BLKB; ilBase = 64 * (bid & 1); }
                epi_store2(sb, tmem, p, V, dst, dArB, ilBase, q);
                fence_before();
                fence_proxy_async_g();
                if (e == 10) red_rel_add1(&g_flags[0]);
                if (e == 11) red_rel_add1(&g_flags[1]);
            }
            mbar_arrive(sb + SM_EPID(p));
        }
    }
    __syncthreads();
    if (wid == 0) tmem_dealloc(tmem, 256);
#else
    (void)W; (void)bias; (void)out;
#endif
}

// ---------------------------------------------------------------------------
extern "C" void kernel_launch(void* const* d_in, const int* in_sizes, int n_in,
                              void* d_out, int out_size)
{
    (void)in_sizes; (void)n_in; (void)out_size;
    const int*   ids  = (const int*)d_in[0];
    const float* emb  = (const float*)d_in[1];
    const float* W    = (const float*)d_in[2];
    const float* bias = (const float*)d_in[3];
    float* out = (float*)d_out;

    static bool attr_set = false;
    if (!attr_set) {
        cudaFuncSetAttribute(precompute_tc, cudaFuncAttributeMaxDynamicSharedMemorySize, DYN_SMEM);
        cudaFuncSetAttribute(fused12_tc,    cudaFuncAttributeMaxDynamicSharedMemorySize, DYN_SMEM);
        cudaFuncSetAttribute(tree2_tc,      cudaFuncAttributeMaxDynamicSharedMemorySize, DYN_SMEM);
        attr_set = true;
    }

    uint4 *elh, *ell, *erh, *erl;
    cudaGetSymbolAddress((void**)&elh, g_ELh);
    cudaGetSymbolAddress((void**)&ell, g_ELl);
    cudaGetSymbolAddress((void**)&erh, g_ERh);
    cudaGetSymbolAddress((void**)&erl, g_ERl);

    clear_flags_k<<<4, 256>>>();
    precompute_tc<<<148, NT_PF, DYN_SMEM>>>(emb, W, elh, ell, erh, erl, VOCABPAD / TILE_M);
    fused12_tc<<<148, NT_PF, DYN_SMEM>>>(ids, elh, ell, erh, erl, W, bias, 1024);
    tree2_tc<<<128, NT_TREE, DYN_SMEM>>>(W, bias, out);
}

// round 14
// speedup vs baseline: 1.3124x; 1.3124x over previous
#include <cuda_runtime.h>
#include <cstdint>

#define VOCAB    100000
#define VOCABPAD 100096
#define DDIM     128
#define KDIM     256
#define NT_PF    448                    // 9 prod + 4 epi + 1 mma warps
#define NT_TREE  256
#define NPROD    288                    // warps 0-8 produce
#define TILE_M   128
#define NSTAGE   3

#define BLKB     131072u
#define CHB      32768u

// arena regions (bytes)
#define SCR_BASE  67108864u
#define SCR_STRIDE 524288u
#define A5OFF     262144u
#define FIN_BASE  134217728u
#define FIN2_BASE 134742016u

#if !defined(__CUDA_ARCH__) || defined(__CUDA_ARCH_FEAT_SM103_ALL) || \
    (defined(__CUDA_ARCH_SPECIFIC__) && (__CUDA_ARCH_SPECIFIC__ == 1030))
#define HAS_TCGEN05 1
#else
#define HAS_TCGEN05 0
#endif

// ---- SMEM frame ----
#define SM_B     0
#define SM_BLO   65536
#define SM_A     131072
#define SM_HDR   229376
#define SM_TMEMP (SM_HDR + 0)
#define SM_FULL(s)  (SM_HDR + 16 + (s) * 8)
#define SM_EMPTY(s) (SM_HDR + 48 + (s) * 8)
#define SM_EPI(p)   (SM_HDR + 80 + (p) * 8)
#define SM_EPID(p)  (SM_HDR + 96 + (p) * 8)
#define SM_BIAS  (SM_HDR + 128)
#define DYN_SMEM 231424

#define IDESC_N128 0x8200490u
#define IDESC_N256 0x8400490u

__device__ uint4 g_tree[8650752];
__device__ int   g_flags[1024];
__device__ float g_EL[VOCABPAD * 128];
__device__ float g_ER[VOCABPAD * 128];

// ---------------- PTX helpers ----------------
__device__ __forceinline__ uint32_t smem_u32(const void* p) {
    uint32_t a;
    asm("{ .reg .u64 t; cvta.to.shared.u64 t, %1; cvt.u32.u64 %0, t; }" : "=r"(a) : "l"(p));
    return a;
}
__device__ __forceinline__ bool elect_one() {
    uint32_t pred;
    asm volatile("{ .reg .pred p; elect.sync _|p, 0xFFFFFFFF; selp.b32 %0, 1, 0, p; }" : "=r"(pred));
    return pred != 0;
}
__device__ __forceinline__ void sts128(uint32_t a, uint32_t x, uint32_t y, uint32_t z, uint32_t w) {
    asm volatile("st.shared.v4.b32 [%0], {%1,%2,%3,%4};" :: "r"(a), "r"(x), "r"(y), "r"(z), "r"(w) : "memory");
}
__device__ __forceinline__ int lds_s32(uint32_t a) {
    int v; asm volatile("ld.shared.b32 %0, [%1];" : "=r"(v) : "r"(a)); return v;
}
__device__ __forceinline__ float4 lds_f32x4(uint32_t a) {
    float4 v;
    asm volatile("ld.shared.v4.f32 {%0,%1,%2,%3}, [%4];"
                 : "=f"(v.x), "=f"(v.y), "=f"(v.z), "=f"(v.w) : "r"(a));
    return v;
}
__device__ __forceinline__ void sts_b32(uint32_t a, uint32_t v) {
    asm volatile("st.shared.b32 [%0], %1;" :: "r"(a), "r"(v) : "memory");
}
__device__ __forceinline__ void mbar_init(uint32_t a, uint32_t c) {
    asm volatile("mbarrier.init.shared.b64 [%0], %1;" :: "r"(a), "r"(c) : "memory");
}
__device__ __forceinline__ void mbar_arrive(uint32_t a) {
    asm volatile("mbarrier.arrive.shared.b64 _, [%0];" :: "r"(a) : "memory");
}
__device__ __forceinline__ void mbar_expect_tx(uint32_t a, uint32_t bytes) {
    asm volatile("mbarrier.arrive.expect_tx.shared.b64 _, [%0], %1;" :: "r"(a), "r"(bytes) : "memory");
}
__device__ __forceinline__ void bulk_g2s(uint32_t dst, const char* src, uint32_t bytes, uint32_t mbar) {
    asm volatile("cp.async.bulk.shared::cluster.global.mbarrier::complete_tx::bytes [%0], [%1], %2, [%3];"
                 :: "r"(dst), "l"(src), "r"(bytes), "r"(mbar) : "memory");
}
__device__ __forceinline__ void fence_proxy_async_s() {
    asm volatile("fence.proxy.async.shared::cta;" ::: "memory");
}
__device__ __forceinline__ void fence_proxy_async_g() {
    asm volatile("fence.proxy.async;" ::: "memory");
}
__device__ __forceinline__ int ld_acq(const int* p) {
    int v; asm volatile("ld.acquire.gpu.global.b32 %0, [%1];" : "=r"(v) : "l"(p) : "memory");
    return v;
}
__device__ __forceinline__ void red_rel_add1(int* p) {
    asm volatile("red.release.gpu.global.add.s32 [%0], 1;" :: "l"(p) : "memory");
}
__device__ __forceinline__ void nsleep() { asm volatile("nanosleep.u32 64;" ::: ); }

#if HAS_TCGEN05
__device__ __forceinline__ void mbar_wait(uint32_t a, uint32_t parity) {
    asm volatile(
        "{\n\t.reg .pred P;\n\t"
        "W%=:\n\t"
        "mbarrier.try_wait.parity.acquire.cta.shared::cta.b64 P, [%0], %1, 0x989680;\n\t"
        "@P bra.uni D%=;\n\t"
        "bra.uni W%=;\n\t"
        "D%=:\n\t}"
        :: "r"(a), "r"(parity) : "memory");
}
__device__ __forceinline__ void tmem_alloc(uint32_t dst, uint32_t n) {
    asm volatile("tcgen05.alloc.cta_group::1.sync.aligned.shared::cta.b32 [%0], %1;"
                 :: "r"(dst), "r"(n) : "memory");
}
__device__ __forceinline__ void tmem_relinquish() {
    asm volatile("tcgen05.relinquish_alloc_permit.cta_group::1.sync.aligned;");
}
__device__ __forceinline__ void tmem_dealloc(uint32_t t, uint32_t n) {
    asm volatile("tcgen05.dealloc.cta_group::1.sync.aligned.b32 %0, %1;" :: "r"(t), "r"(n));
}
__device__ __forceinline__ void mma_f16_ss(uint32_t d, uint64_t ad, uint64_t bd, uint32_t idesc, uint32_t en) {
    asm volatile(
        "{\n\t.reg .pred p;\n\tsetp.ne.u32 p, %4, 0;\n\t"
        "tcgen05.mma.cta_group::1.kind::f16 [%0], %1, %2, %3, {%5,%5,%5,%5}, p;\n\t}"
        :: "r"(d), "l"(ad), "l"(bd), "r"(idesc), "r"(en), "r"(0u) : "memory");
}
__device__ __forceinline__ void mma_commit(uint32_t mbar) {
    asm volatile("tcgen05.commit.cta_group::1.mbarrier::arrive::one.shared::cluster.b64 [%0];"
                 :: "r"(mbar) : "memory");
}
__device__ __forceinline__ void fence_after()  { asm volatile("tcgen05.fence::after_thread_sync;"  ::: "memory"); }
__device__ __forceinline__ void fence_before() { asm volatile("tcgen05.fence::before_thread_sync;" ::: "memory"); }
__device__ __forceinline__ void wait_ld()      { asm volatile("tcgen05.wait::ld.sync.aligned;"     ::: "memory"); }
__device__ __forceinline__ void ldtm32(uint32_t* r, uint32_t ta) {
    asm volatile(
        "tcgen05.ld.sync.aligned.32x32b.x32.b32 "
        "{%0, %1, %2, %3, %4, %5, %6, %7, "
        " %8, %9, %10, %11, %12, %13, %14, %15, "
        " %16, %17, %18, %19, %20, %21, %22, %23, "
        " %24, %25, %26, %27, %28, %29, %30, %31}, [%32];"
        : "=r"(r[0]), "=r"(r[1]), "=r"(r[2]), "=r"(r[3]),
          "=r"(r[4]), "=r"(r[5]), "=r"(r[6]), "=r"(r[7]),
          "=r"(r[8]), "=r"(r[9]), "=r"(r[10]), "=r"(r[11]),
          "=r"(r[12]), "=r"(r[13]), "=r"(r[14]), "=r"(r[15]),
          "=r"(r[16]), "=r"(r[17]), "=r"(r[18]), "=r"(r[19]),
          "=r"(r[20]), "=r"(r[21]), "=r"(r[22]), "=r"(r[23]),
          "=r"(r[24]), "=r"(r[25]), "=r"(r[26]), "=r"(r[27]),
          "=r"(r[28]), "=r"(r[29]), "=r"(r[30]), "=r"(r[31])
        : "r"(ta));
}
#endif // HAS_TCGEN05

__device__ __forceinline__ uint32_t swz(uint32_t off) { return off ^ ((off >> 3) & 0x70); }

__device__ __forceinline__ uint64_t mk_desc(uint32_t addr) {
    const uint64_t base = (uint64_t(2) << 61) | (uint64_t(1) << 46) |
                          (uint64_t(64) << 32) | (uint64_t(1) << 16);
    return base | ((uint64_t)(addr >> 4) & 0x3FFF);
}

// split 8 fp32 -> bf16 hi + exact-residual bf16 lo
__device__ __forceinline__ void split8(const float4& v0, const float4& v1, uint4& h, uint4& l) {
    float f[8] = {v0.x, v0.y, v0.z, v0.w, v1.x, v1.y, v1.z, v1.w};
    uint32_t hh[4], ll[4];
#pragma unroll
    for (int q = 0; q < 4; q++) {
        float a = f[2 * q], b = f[2 * q + 1];
        uint32_t hv;
        asm("cvt.rn.bf16x2.f32 %0, %1, %2;" : "=r"(hv) : "f"(b), "f"(a));
        hh[q] = hv;
        float ha = __uint_as_float(hv << 16);
        float hb = __uint_as_float(hv & 0xFFFF0000u);
        asm("cvt.rn.bf16x2.f32 %0, %1, %2;" : "=r"(ll[q]) : "f"(b - hb), "f"(a - ha));
    }
    h = make_uint4(hh[0], hh[1], hh[2], hh[3]);
    l = make_uint4(ll[0], ll[1], ll[2], ll[3]);
}

#if HAS_TCGEN05
// 12 split-MMAs for one K=64 chunk (A in ring stage s, B chunk c)
__device__ __forceinline__ void mma_chunk(uint32_t dA, uint32_t sb, int s, int c, bool first) {
    const uint32_t aHi = sb + SM_A + s * 32768;
    const uint64_t adh = mk_desc(aHi), adl = mk_desc(aHi + 16384);
    const uint64_t bdh = mk_desc(sb + SM_B + c * 16384);
    const uint64_t bdl = mk_desc(sb + SM_BLO + c * 16384);
#pragma unroll
    for (int ks = 0; ks < 4; ks++)
        mma_f16_ss(dA, adh + 2 * ks, bdh + 2 * ks, IDESC_N128, (!first || ks > 0) ? 1u : 0u);
#pragma unroll
    for (int ks = 0; ks < 4; ks++)
        mma_f16_ss(dA, adh + 2 * ks, bdl + 2 * ks, IDESC_N128, 1u);
#pragma unroll
    for (int ks = 0; ks < 4; ks++)
        mma_f16_ss(dA, adl + 2 * ks, bdh + 2 * ks, IDESC_N128, 1u);
}

// direct-SMEM compact A block at sb+SM_A
__device__ __forceinline__ void mma_chunk_direct(uint32_t dA, uint32_t sb, uint32_t half, int c, bool first) {
    const uint32_t b0 = sb + SM_A + (uint32_t)c * 2u * half;
    const uint64_t adh = mk_desc(b0), adl = mk_desc(b0 + half);
    const uint64_t bdh = mk_desc(sb + SM_B + c * 16384);
    const uint64_t bdl = mk_desc(sb + SM_BLO + c * 16384);
#pragma unroll
    for (int ks = 0; ks < 4; ks++)
        mma_f16_ss(dA, adh + 2 * ks, bdh + 2 * ks, IDESC_N128, (!first || ks > 0) ? 1u : 0u);
#pragma unroll
    for (int ks = 0; ks < 4; ks++)
        mma_f16_ss(dA, adh + 2 * ks, bdl + 2 * ks, IDESC_N128, 1u);
#pragma unroll
    for (int ks = 0; ks < 4; ks++)
        mma_f16_ss(dA, adl + 2 * ks, bdh + 2 * ks, IDESC_N128, 1u);
}

// fused12 epilogue: fixed 128-row consumer blocks (GMEM)
__device__ __forceinline__ void epi_store_chunked(uint32_t sb, uint32_t tmem, int p,
                                                  int tau, char* consBase, int q) {
    char* blkBase = consBase + (size_t)(tau >> 1) * BLKB;
    const int il = 64 * (tau & 1) + (q >> 1);
    const int cpar = 2 * (q & 1);
#pragma unroll
    for (int qq = 0; qq < 4; qq++) {
        uint32_t d[32];
        ldtm32(d, tmem + p * 128 + qq * 32);
        wait_ld();
        char* cb = blkBase + (size_t)(cpar + (qq >> 1)) * CHB;
#pragma unroll
        for (int u = 0; u < 4; u++) {
            float4 bv0 = lds_f32x4(sb + SM_BIAS + (qq * 32 + u * 8) * 4);
            float4 bv1 = lds_f32x4(sb + SM_BIAS + (qq * 32 + u * 8 + 4) * 4);
            float4 v0, v1;
            v0.x = __uint_as_float(d[8*u+0]) + bv0.x; v0.y = __uint_as_float(d[8*u+1]) + bv0.y;
            v0.z = __uint_as_float(d[8*u+2]) + bv0.z; v0.w = __uint_as_float(d[8*u+3]) + bv0.w;
            v1.x = __uint_as_float(d[8*u+4]) + bv1.x; v1.y = __uint_as_float(d[8*u+5]) + bv1.y;
            v1.z = __uint_as_float(d[8*u+6]) + bv1.z; v1.w = __uint_as_float(d[8*u+7]) + bv1.w;
            uint4 h, l; split8(v0, v1, h, l);
            const uint32_t off = swz((uint32_t)il * 128 + (32 * (qq & 1) + 8 * u) * 2);
            *(uint4*)(cb + off) = h;
            *(uint4*)(cb + 16384 + off) = l;
        }
    }
}

// generalized epilogue store to GMEM block (whole-warp skip when slice invalid)
__device__ __forceinline__ void epi_store2(uint32_t sb, uint32_t tmem, int p, int V,
                                           char* dst, uint32_t dArB, int ilBase, int q) {
    if ((q & ~31) >= V) return;
    const uint32_t chbd = 2 * dArB;
#pragma unroll
    for (int qq = 0; qq < 4; qq++) {
        uint32_t d[32];
        ldtm32(d, tmem + p * 128 + qq * 32);
        wait_ld();
        if (q < V) {
            const int il = ilBase + (q >> 1);
            char* cb = dst + (size_t)(2 * (q & 1) + (qq >> 1)) * chbd;
#pragma unroll
            for (int u = 0; u < 4; u++) {
                float4 bv0 = lds_f32x4(sb + SM_BIAS + (qq * 32 + u * 8) * 4);
                float4 bv1 = lds_f32x4(sb + SM_BIAS + (qq * 32 + u * 8 + 4) * 4);
                float4 v0, v1;
                v0.x = __uint_as_float(d[8*u+0]) + bv0.x; v0.y = __uint_as_float(d[8*u+1]) + bv0.y;
                v0.z = __uint_as_float(d[8*u+2]) + bv0.z; v0.w = __uint_as_float(d[8*u+3]) + bv0.w;
                v1.x = __uint_as_float(d[8*u+4]) + bv1.x; v1.y = __uint_as_float(d[8*u+5]) + bv1.y;
                v1.z = __uint_as_float(d[8*u+6]) + bv1.z; v1.w = __uint_as_float(d[8*u+7]) + bv1.w;
                uint4 h, l; split8(v0, v1, h, l);
                const uint32_t off = swz((uint32_t)il * 128 + (32 * (qq & 1) + 8 * u) * 2);
                *(uint4*)(cb + off) = h;
                *(uint4*)(cb + dArB + off) = l;
            }
        }
    }
}

// epilogue store into SMEM compact block (whole-warp skip when slice invalid)
__device__ __forceinline__ void epi_store2_smem(uint32_t sb, uint32_t tmem, int p, int V,
                                                uint32_t dstBase, uint32_t dArB, int q) {
    if ((q & ~31) >= V) return;
    const uint32_t chbd = 2 * dArB;
#pragma unroll
    for (int qq = 0; qq < 4; qq++) {
        uint32_t d[32];
        ldtm32(d, tmem + p * 128 + qq * 32);
        wait_ld();
        if (q < V) {
            const int il = q >> 1;
            uint32_t cb = dstBase + (uint32_t)(2 * (q & 1) + (qq >> 1)) * chbd;
#pragma unroll
            for (int u = 0; u < 4; u++) {
                float4 bv0 = lds_f32x4(sb + SM_BIAS + (qq * 32 + u * 8) * 4);
                float4 bv1 = lds_f32x4(sb + SM_BIAS + (qq * 32 + u * 8 + 4) * 4);
                float4 v0, v1;
                v0.x = __uint_as_float(d[8*u+0]) + bv0.x; v0.y = __uint_as_float(d[8*u+1]) + bv0.y;
                v0.z = __uint_as_float(d[8*u+2]) + bv0.z; v0.w = __uint_as_float(d[8*u+3]) + bv0.w;
                v1.x = __uint_as_float(d[8*u+4]) + bv1.x; v1.y = __uint_as_float(d[8*u+5]) + bv1.y;
                v1.z = __uint_as_float(d[8*u+6]) + bv1.z; v1.w = __uint_as_float(d[8*u+7]) + bv1.w;
                uint4 h, l; split8(v0, v1, h, l);
                const uint32_t off = swz((uint32_t)il * 128 + (32 * (qq & 1) + 8 * u) * 2);
                sts128(cb + off, h.x, h.y, h.z, h.w);
                sts128(cb + dArB + off, l.x, l.y, l.z, l.w);
            }
        }
    }
}
#endif

// ---------------------------------------------------------------------------
__global__ void clear_flags_k() {
    int i = blockIdx.x * 256 + threadIdx.x;
    if (i < 1024) g_flags[i] = 0;
}

// ---------------------------------------------------------------------------
// Precompute: EL/ER. Producers warps 0-8 (288, pipelined); epi warps 9-12;
// MMA warp 13.
// ---------------------------------------------------------------------------
__global__ __launch_bounds__(NT_PF, 1)
void precompute_tc(const float* __restrict__ emb, const float* __restrict__ W,
                   float* __restrict__ EL, float* __restrict__ ER, int numTiles)
{
#if HAS_TCGEN05
    extern __shared__ char dsm[];
    const uint32_t sb = (smem_u32(dsm) + 1023) & ~1023u;
    const int tid = threadIdx.x, wid = tid >> 5, lid = tid & 31;

    if (tid == 0) {
#pragma unroll
        for (int s = 0; s < NSTAGE; s++) { mbar_init(SM_FULL(s) + sb, NPROD); mbar_init(SM_EMPTY(s) + sb, 1); }
#pragma unroll
        for (int p = 0; p < 2; p++) { mbar_init(SM_EPI(p) + sb, 1); mbar_init(SM_EPID(p) + sb, 128); }
    }
    if (tid < 256) {
        const int n = tid;
        const float* wrow = W + (size_t)(n & 127) * KDIM + (n >> 7) * 128;
#pragma unroll
        for (int g = 0; g < 16; g++) {
            int k0 = g * 8;
            float4 v0 = *(const float4*)(wrow + k0);
            float4 v1 = *(const float4*)(wrow + k0 + 4);
            uint4 h, l; split8(v0, v1, h, l);
            uint32_t off = (k0 >> 6) * 32768 + swz(n * 128 + (k0 & 63) * 2);
            sts128(sb + SM_B + off, h.x, h.y, h.z, h.w);
            sts128(sb + SM_BLO + off, l.x, l.y, l.z, l.w);
        }
    }
    fence_proxy_async_s();
    __syncthreads();
    if (wid == 0) { tmem_alloc(sb + SM_TMEMP, 512); tmem_relinquish(); }
    __syncthreads();
    const uint32_t tmem = (uint32_t)lds_s32(sb + SM_TMEMP);

    const bool mmaLead = (wid == 13) && elect_one();
    int uc[NSTAGE] = {0, 0, 0}, fc[NSTAGE] = {0, 0, 0}, tp[2] = {0, 0}, epc[2] = {0, 0};
    int tl = 0, prevRow = 0;

    for (int tile = blockIdx.x; tile < numTiles; tile += gridDim.x) {
        const int tileRow = tile * TILE_M;
        if (tid < NPROD) {
#pragma unroll
            for (int c = 0; c < 2; c++) {
                const int s = (tl * 2 + c) % NSTAGE;
                const uint32_t hiB = sb + SM_A + s * 32768, loB = hiB + 16384;

                int i0 = tid;
                int er0 = tileRow + (i0 >> 3); if (er0 > VOCAB - 1) er0 = VOCAB - 1;
                const float* s0 = emb + (size_t)er0 * DDIM + c * 64 + (i0 & 7) * 8;
                float4 v0 = *(const float4*)s0;
                float4 v1 = *(const float4*)(s0 + 4);
                int i1 = i0 + NPROD;

                if (uc[s] > 0) mbar_wait(sb + SM_EMPTY(s), (uc[s] - 1) & 1);
                uc[s]++;

                while (true) {
                    float4 nv0, nv1;
                    if (i1 < 1024) {
                        int er1 = tileRow + (i1 >> 3); if (er1 > VOCAB - 1) er1 = VOCAB - 1;
                        const float* s1 = emb + (size_t)er1 * DDIM + c * 64 + (i1 & 7) * 8;
                        nv0 = *(const float4*)s1;
                        nv1 = *(const float4*)(s1 + 4);
                    }
                    uint4 h, l; split8(v0, v1, h, l);
                    const uint32_t off = swz((i0 >> 3) * 128 + (i0 & 7) * 16);
                    sts128(hiB + off, h.x, h.y, h.z, h.w);
                    sts128(loB + off, l.x, l.y, l.z, l.w);
                    if (i1 >= 1024) break;
                    i0 = i1; v0 = nv0; v1 = nv1; i1 += NPROD;
                }
                fence_proxy_async_s();
                mbar_arrive(sb + SM_FULL(s));
            }
        } else if (mmaLead) {
            const int p = tl & 1;
            if (tp[p] > 0) mbar_wait(sb + SM_EPID(p), (tp[p] - 1) & 1);
            tp[p]++;
            const uint32_t dA = tmem + p * 256;
#pragma unroll
            for (int c = 0; c < 2; c++) {
                const int s = (tl * 2 + c) % NSTAGE;
                mbar_wait(sb + SM_FULL(s), fc[s] & 1); fc[s]++;
                const uint32_t aHi = sb + SM_A + s * 32768;
                const uint64_t adh = mk_desc(aHi), adl = mk_desc(aHi + 16384);
                const uint64_t bdh = mk_desc(sb + SM_B + c * 32768);
                const uint64_t bdl = mk_desc(sb + SM_BLO + c * 32768);
#pragma unroll
                for (int ks = 0; ks < 4; ks++)
                    mma_f16_ss(dA, adh + 2 * ks, bdh + 2 * ks, IDESC_N256, (c > 0 || ks > 0) ? 1u : 0u);
#pragma unroll
                for (int ks = 0; ks < 4; ks++)
                    mma_f16_ss(dA, adh + 2 * ks, bdl + 2 * ks, IDESC_N256, 1u);
#pragma unroll
                for (int ks = 0; ks < 4; ks++)
                    mma_f16_ss(dA, adl + 2 * ks, bdh + 2 * ks, IDESC_N256, 1u);
                mma_commit(sb + SM_EMPTY(s));
            }
            mma_commit(sb + SM_EPI(p));
        } else if (wid >= 9 && wid <= 12 && tl >= 1) {
            const int p = (tl - 1) & 1;
            mbar_wait(sb + SM_EPI(p), epc[p] & 1); epc[p]++;
            fence_after();
            const int rowg = prevRow + (wid & 3) * 32 + lid;
#pragma unroll
            for (int q = 0; q < 8; q++) {
                uint32_t d[32];
                ldtm32(d, tmem + p * 256 + q * 32);
                wait_ld();
                const int col0 = q * 32;
                float* dst = (col0 < 128 ? EL + (size_t)rowg * DDIM + col0
                                         : ER + (size_t)rowg * DDIM + (col0 - 128));
#pragma unroll
                for (int u = 0; u < 8; u++)
                    *(float4*)(dst + u * 4) =
                        make_float4(__uint_as_float(d[4*u+0]), __uint_as_float(d[4*u+1]),
                                    __uint_as_float(d[4*u+2]), __uint_as_float(d[4*u+3]));
            }
            fence_before();
            mbar_arrive(sb + SM_EPID(p));
        }
        prevRow = tileRow; tl++;
    }

    if (wid >= 9 && wid <= 12 && tl >= 1) {
        const int p = (tl - 1) & 1;
        mbar_wait(sb + SM_EPI(p), epc[p] & 1); epc[p]++;
        fence_after();
        const int rowg = prevRow + (wid & 3) * 32 + lid;
#pragma unroll
        for (int q = 0; q < 8; q++) {
            uint32_t d[32];
            ldtm32(d, tmem + p * 256 + q * 32);
            wait_ld();
            const int col0 = q * 32;
            float* dst = (col0 < 128 ? EL + (size_t)rowg * DDIM + col0
                                     : ER + (size_t)rowg * DDIM + (col0 - 128));
#pragma unroll
            for (int u = 0; u < 8; u++)
                *(float4*)(dst + u * 4) =
                    make_float4(__uint_as_float(d[4*u+0]), __uint_as_float(d[4*u+1]),
                                __uint_as_float(d[4*u+2]), __uint_as_float(d[4*u+3]));
        }
        fence_before();
    }
    __syncthreads();
    if (wid == 0) tmem_dealloc(tmem, 512);
#else
    (void)emb; (void)W; (void)EL; (void)ER; (void)numTiles;
#endif
}

// ---------------------------------------------------------------------------
// Fused levels 1+2 (gather): producers warps 0-8 (288, 2-deep pipelined);
// epi warps 9-12; MMA warp 13.
// ---------------------------------------------------------------------------
__global__ __launch_bounds__(NT_PF, 1)
void fused12_tc(const int* __restrict__ ids,
                const float* __restrict__ EL, const float* __restrict__ ER,
                const float* __restrict__ W, const float* __restrict__ bias, int numTiles)
{
#if HAS_TCGEN05
    extern __shared__ char dsm[];
    const uint32_t sb = (smem_u32(dsm) + 1023) & ~1023u;
    const int tid = threadIdx.x, wid = tid >> 5, lid = tid & 31;
    char* arena = (char*)g_tree;

    if (tid == 0) {
#pragma unroll
        for (int s = 0; s < NSTAGE; s++) { mbar_init(SM_FULL(s) + sb, NPROD); mbar_init(SM_EMPTY(s) + sb, 1); }
#pragma unroll
        for (int p = 0; p < 2; p++) { mbar_init(SM_EPI(p) + sb, 1); mbar_init(SM_EPID(p) + sb, 128); }
    }
    if (tid < 128) sts_b32(sb + SM_BIAS + tid * 4, __float_as_uint(bias[tid]));

    if (tid < 256) {
        const int n = tid >> 1, h2 = tid & 1;
#pragma unroll
        for (int g = 0; g < 16; g++) {
            int k0 = h2 * 128 + g * 8;
            float4 v0 = *(const float4*)(W + (size_t)n * KDIM + k0);
            float4 v1 = *(const float4*)(W + (size_t)n * KDIM + k0 + 4);
            uint4 h, l; split8(v0, v1, h, l);
            uint32_t off = (k0 >> 6) * 16384 + swz(n * 128 + (k0 & 63) * 2);
            sts128(sb + SM_B + off, h.x, h.y, h.z, h.w);
            sts128(sb + SM_BLO + off, l.x, l.y, l.z, l.w);
        }
    }
    fence_proxy_async_s();
    __syncthreads();
    if (wid == 0) { tmem_alloc(sb + SM_TMEMP, 256); tmem_relinquish(); }
    __syncthreads();
    const uint32_t tmem = (uint32_t)lds_s32(sb + SM_TMEMP);

    const bool mmaLead = (wid == 13) && elect_one();
    int uc[NSTAGE] = {0, 0, 0}, fc[NSTAGE] = {0, 0, 0}, tp[2] = {0, 0}, epc[2] = {0, 0};
    int tl = 0, prevTile = 0;

    for (int tile = blockIdx.x; tile < numTiles; tile += gridDim.x) {
        const int tileRow = tile * TILE_M;
        if (tid < NPROD) {
#pragma unroll
            for (int c = 0; c < 4; c++) {
                const int s = (tl * 4 + c) % NSTAGE;
                const uint32_t hiB = sb + SM_A + s * 32768, loB = hiB + 16384;
                const int ch = c >> 1, sub0 = (c & 1) * 64;

                int i0 = tid;
                int2 id0 = *(const int2*)(ids + 2 * (2 * (tileRow + (i0 >> 3)) + ch));
                const float* pl0 = EL + (size_t)id0.x * DDIM + sub0 + (i0 & 7) * 8;
                const float* pr0 = ER + (size_t)id0.y * DDIM + sub0 + (i0 & 7) * 8;
                float4 l0 = *(const float4*)pl0,       l1 = *(const float4*)(pl0 + 4);
                float4 r0 = *(const float4*)pr0,       r1 = *(const float4*)(pr0 + 4);
                int i1 = i0 + NPROD;
                int2 id1;
                if (i1 < 1024)
                    id1 = *(const int2*)(ids + 2 * (2 * (tileRow + (i1 >> 3)) + ch));

                if (uc[s] > 0) mbar_wait(sb + SM_EMPTY(s), (uc[s] - 1) & 1);
                uc[s]++;

                while (true) {
                    float4 nl0, nl1, nr0, nr1;
                    if (i1 < 1024) {
                        const float* pl1 = EL + (size_t)id1.x * DDIM + sub0 + (i1 & 7) * 8;
                        const float* pr1 = ER + (size_t)id1.y * DDIM + sub0 + (i1 & 7) * 8;
                        nl0 = *(const float4*)pl1; nl1 = *(const float4*)(pl1 + 4);
                        nr0 = *(const float4*)pr1; nr1 = *(const float4*)(pr1 + 4);
                    }
                    int i2 = i1 + NPROD;
                    int2 id2;
                    if (i2 < 1024)
                        id2 = *(const int2*)(ids + 2 * (2 * (tileRow + (i2 >> 3)) + ch));

                    {
                        const int sub = sub0 + (i0 & 7) * 8;
                        float4 b0 = lds_f32x4(sb + SM_BIAS + sub * 4);
                        float4 b1 = lds_f32x4(sb + SM_BIAS + (sub + 4) * 4);
                        float4 v0, v1;
                        v0.x = l0.x + r0.x + b0.x; v0.y = l0.y + r0.y + b0.y;
                        v0.z = l0.z + r0.z + b0.z; v0.w = l0.w + r0.w + b0.w;
                        v1.x = l1.x + r1.x + b1.x; v1.y = l1.y + r1.y + b1.y;
                        v1.z = l1.z + r1.z + b1.z; v1.w = l1.w + r1.w + b1.w;
                        uint4 h, l; split8(v0, v1, h, l);
                        const uint32_t off = swz((i0 >> 3) * 128 + (i0 & 7) * 16);
                        sts128(hiB + off, h.x, h.y, h.z, h.w);
                        sts128(loB + off, l.x, l.y, l.z, l.w);
                    }
                    if (i1 >= 1024) break;
                    i0 = i1; l0 = nl0; l1 = nl1; r0 = nr0; r1 = nr1;
                    id1 = id2; i1 = i2;
                }
                fence_proxy_async_s();
                mbar_arrive(sb + SM_FULL(s));
            }
        } else if (mmaLead) {
            const int p = tl & 1;
            if (tp[p] > 0) mbar_wait(sb + SM_EPID(p), (tp[p] - 1) & 1);
            tp[p]++;
            const uint32_t dA = tmem + p * 128;
#pragma unroll
            for (int c = 0; c < 4; c++) {
                const int s = (tl * 4 + c) % NSTAGE;
                mbar_wait(sb + SM_FULL(s), fc[s] & 1); fc[s]++;
                mma_chunk(dA, sb, s, c, c == 0);
                mma_commit(sb + SM_EMPTY(s));
            }
            mma_commit(sb + SM_EPI(p));
        } else if (wid >= 9 && wid <= 12 && tl >= 1) {
            const int p = (tl - 1) & 1;
            mbar_wait(sb + SM_EPI(p), epc[p] & 1); epc[p]++;
            fence_after();
            epi_store_chunked(sb, tmem, p, prevTile, arena, (wid & 3) * 32 + lid);
            fence_before();
            fence_proxy_async_g();
            mbar_arrive(sb + SM_EPID(p));
        }
        prevTile = tile; tl++;
    }

    if (wid >= 9 && wid <= 12 && tl >= 1) {
        const int p = (tl - 1) & 1;
        mbar_wait(sb + SM_EPI(p), epc[p] & 1); epc[p]++;
        fence_after();
        epi_store_chunked(sb, tmem, p, prevTile, arena, (wid & 3) * 32 + lid);
        fence_before();
        fence_proxy_async_g();
    }
    __syncthreads();
    if (wid == 0) tmem_dealloc(tmem, 256);
#else
    (void)ids; (void)EL; (void)ER; (void)W; (void)bias; (void)numTiles;
#endif
}

// ---------------------------------------------------------------------------
// Tree kernel: 128 CTAs local cascade; TMA issues hoisted ahead of D-reuse
// waits; gemms 7-10 direct-SMEM A; small-V epilogues skip invalid warps.
// ---------------------------------------------------------------------------
__global__ __launch_bounds__(NT_TREE, 1)
void tree2_tc(const float* __restrict__ W, const float* __restrict__ bias,
              float* __restrict__ out)
{
#if HAS_TCGEN05
    extern __shared__ char dsm[];
    const uint32_t sb = (smem_u32(dsm) + 1023) & ~1023u;
    const int tid = threadIdx.x, wid = tid >> 5, lid = tid & 31;
    const int bid = blockIdx.x;
    char* arena = (char*)g_tree;
    char* S    = arena + SCR_BASE + (size_t)bid * SCR_STRIDE;
    char* FIN  = arena + FIN_BASE;
    char* FIN2 = arena + FIN2_BASE;

    if (tid == 0) {
#pragma unroll
        for (int s = 0; s < NSTAGE; s++) { mbar_init(SM_FULL(s) + sb, 1); mbar_init(SM_EMPTY(s) + sb, 1); }
#pragma unroll
        for (int p = 0; p < 2; p++) { mbar_init(SM_EPI(p) + sb, 1); mbar_init(SM_EPID(p) + sb, 128); }
    }
    if (tid < 128) sts_b32(sb + SM_BIAS + tid * 4, __float_as_uint(bias[tid]));

    {   // B = W chunks
        const int n = tid >> 1, h2 = tid & 1;
#pragma unroll
        for (int g = 0; g < 16; g++) {
            int k0 = h2 * 128 + g * 8;
            float4 v0 = *(const float4*)(W + (size_t)n * KDIM + k0);
            float4 v1 = *(const float4*)(W + (size_t)n * KDIM + k0 + 4);
            uint4 h, l; split8(v0, v1, h, l);
            uint32_t off = (k0 >> 6) * 16384 + swz(n * 128 + (k0 & 63) * 2);
            sts128(sb + SM_B + off, h.x, h.y, h.z, h.w);
            sts128(sb + SM_BLO + off, l.x, l.y, l.z, l.w);
        }
    }
    fence_proxy_async_s();
    __syncthreads();
    if (wid == 0) { tmem_alloc(sb + SM_TMEMP, 256); tmem_relinquish(); }
    __syncthreads();
    const uint32_t tmem = (uint32_t)lds_s32(sb + SM_TMEMP);

    const int nG = 11 + (bid < 4 ? 1 : 0) + (bid < 2 ? 1 : 0);

    if (wid == 7 && elect_one()) {
        int kChunk = 0;
        int issued[NSTAGE] = {0, 0, 0}, fcons[NSTAGE] = {0, 0, 0};
        int epidW[2] = {0, 0};
        int epiSeen = -1;
        auto waitEpi = [&](int e) {
            while (epiSeen < e) {
                epiSeen++;
                const int pp = epiSeen & 1;
                mbar_wait(sb + SM_EPID(pp), epidW[pp] & 1);
                epidW[pp]++;
            }
        };
        auto issueChunk = [&](int k, const char* src, uint32_t half, int c) {
            const int s = k % NSTAGE;
            if (issued[s] > 0) mbar_wait(sb + SM_EMPTY(s), (issued[s] - 1) & 1);
            issued[s]++;
            mbar_expect_tx(sb + SM_FULL(s), 2 * half);
            bulk_g2s(sb + SM_A + s * 32768,         src + (size_t)c * 2 * half,        half, sb + SM_FULL(s));
            bulk_g2s(sb + SM_A + s * 32768 + 16384, src + (size_t)c * 2 * half + half, half, sb + SM_FULL(s));
        };

        for (int g = 0; g < nG; g++) {
            const int p = g & 1;
            const uint32_t dA = tmem + p * 128;

            if (g >= 7 && g <= 10) {
                // SMEM-direct A (written by epi g-1): full wait required before MMA
                waitEpi(g - 1);
                const uint32_t half = (g == 7) ? 8192u : (g == 8) ? 4096u : (g == 9) ? 2048u : 1024u;
#pragma unroll
                for (int c = 0; c < 4; c++)
                    mma_chunk_direct(dA, sb, half, c, c == 0);
            } else {
                // ---- hoisted TMA-issue dependencies (source availability only) ----
                if (g == 4) waitEpi(1);
                else if (g == 5) waitEpi(3);
                else if (g == 6) waitEpi(5);
                if (g == 11) { while (ld_acq(&g_flags[0]) < 16384) nsleep(); }
                if (g == 12) { while (ld_acq(&g_flags[1]) < 512)   nsleep(); }

                const char* src; uint32_t half = 16384;
                if (g < 4)       src = arena + (size_t)(4 * bid + g) * BLKB;
                else if (g == 4) src = S;
                else if (g == 5) src = S + BLKB;
                else if (g == 6) src = S + A5OFF;
                else if (g == 11) src = FIN + (size_t)bid * BLKB;
                else              src = FIN2 + (size_t)bid * BLKB;

                issueChunk(kChunk + 0, src, half, 0);
                issueChunk(kChunk + 1, src, half, 1);
                issueChunk(kChunk + 2, src, half, 2);

                // ---- D-buffer reuse dependency before first MMA ----
                if (g == 2 || g == 3) waitEpi(g - 2);
                else if (g == 4) waitEpi(2);
                else if (g >= 11) waitEpi(g - 1);
                // g==5: waited epi3 (= g-2) above; g==6: waited epi5 (>= g-2) above

                { const int s = kChunk % NSTAGE;
                  mbar_wait(sb + SM_FULL(s), fcons[s] & 1); fcons[s]++;
                  mma_chunk(dA, sb, s, 0, true);
                  mma_commit(sb + SM_EMPTY(s)); }
                issueChunk(kChunk + 3, src, half, 3);
#pragma unroll
                for (int c = 1; c < 4; c++) {
                    const int s = (kChunk + c) % NSTAGE;
                    mbar_wait(sb + SM_FULL(s), fcons[s] & 1); fcons[s]++;
                    mma_chunk(dA, sb, s, c, false);
                    mma_commit(sb + SM_EMPTY(s));
                }
                kChunk += 4;
            }
            mma_commit(sb + SM_EPI(p));
        }
    } else if (wid < 4) {
        int epc[2] = {0, 0};
        const int q = wid * 32 + lid;
        for (int e = 0; e < nG; e++) {
            const int p = e & 1;
            mbar_wait(sb + SM_EPI(p), epc[p] & 1); epc[p]++;
            fence_after();
            if (e == 12) {
                float* op = out + (size_t)(128 * bid + q) * DDIM;
#pragma unroll
                for (int qq = 0; qq < 4; qq++) {
                    uint32_t d[32];
                    ldtm32(d, tmem + p * 128 + qq * 32);
                    wait_ld();
#pragma unroll
                    for (int u = 0; u < 8; u++) {
                        float4 bv = lds_f32x4(sb + SM_BIAS + (qq * 32 + u * 4) * 4);
                        *(float4*)(op + qq * 32 + u * 4) =
                            make_float4(__uint_as_float(d[4*u+0]) + bv.x, __uint_as_float(d[4*u+1]) + bv.y,
                                        __uint_as_float(d[4*u+2]) + bv.z, __uint_as_float(d[4*u+3]) + bv.w);
                    }
                }
                fence_before();
            } else if (e >= 6 && e <= 9) {
                const uint32_t dArB = (e == 6) ? 8192u : (e == 7) ? 4096u : (e == 8) ? 2048u : 1024u;
                const int V = (e == 6) ? 128 : (e == 7) ? 64 : (e == 8) ? 32 : 16;
                epi_store2_smem(sb, tmem, p, V, sb + SM_A, dArB, q);
                fence_before();
                fence_proxy_async_s();
            } else {
                int V, ilBase; char* dst; uint32_t dArB = 16384;
                if (e < 6)       { V = 128; dst = S + (size_t)(e >> 1) * BLKB; ilBase = 64 * (e & 1); }
                else if (e == 10){ V = 8;   dst = FIN + (size_t)(bid >> 5) * BLKB; ilBase = 4 * (bid & 31); }
                else             { V = 128; dst = FIN2 + (size_t)(bid >> 1) * BLKB; ilBase = 64 * (bid & 1); }
                epi_store2(sb, tmem, p, V, dst, dArB, ilBase, q);
                fence_before();
                fence_proxy_async_g();
                if (e == 10) red_rel_add1(&g_flags[0]);
                if (e == 11) red_rel_add1(&g_flags[1]);
            }
            mbar_arrive(sb + SM_EPID(p));
        }
    }
    __syncthreads();
    if (wid == 0) tmem_dealloc(tmem, 256);
#else
    (void)W; (void)bias; (void)out;
#endif
}

// ---------------------------------------------------------------------------
extern "C" void kernel_launch(void* const* d_in, const int* in_sizes, int n_in,
                              void* d_out, int out_size)
{
    (void)in_sizes; (void)n_in; (void)out_size;
    const int*   ids  = (const int*)d_in[0];
    const float* emb  = (const float*)d_in[1];
    const float* W    = (const float*)d_in[2];
    const float* bias = (const float*)d_in[3];
    float* out = (float*)d_out;

    static bool attr_set = false;
    if (!attr_set) {
        cudaFuncSetAttribute(precompute_tc, cudaFuncAttributeMaxDynamicSharedMemorySize, DYN_SMEM);
        cudaFuncSetAttribute(fused12_tc,    cudaFuncAttributeMaxDynamicSharedMemorySize, DYN_SMEM);
        cudaFuncSetAttribute(tree2_tc,      cudaFuncAttributeMaxDynamicSharedMemorySize, DYN_SMEM);
        attr_set = true;
    }

    float *elp, *erp;
    cudaGetSymbolAddress((void**)&elp, g_EL);
    cudaGetSymbolAddress((void**)&erp, g_ER);

    clear_flags_k<<<4, 256>>>();
    precompute_tc<<<148, NT_PF, DYN_SMEM>>>(emb, W, elp, erp, VOCABPAD / TILE_M);
    fused12_tc<<<148, NT_PF, DYN_SMEM>>>(ids, elp, erp, W, bias, 1024);
    tree2_tc<<<128, NT_TREE, DYN_SMEM>>>(W, bias, out);
}

// round 15
// speedup vs baseline: 1.3154x; 1.0023x over previous
#include <cuda_runtime.h>
#include <cstdint>

#define VOCAB    100000
#define VOCABPAD 100096
#define DDIM     128
#define KDIM     256
#define NT_PF    448                    // 9 prod + 4 epi + 1 mma warps
#define NT_TREE  288                    // 8 epi + 1 issuer warps
#define NPROD    288
#define TILE_M   128
#define NSTAGE   3

#define BLKB     131072u
#define CHB      32768u

// arena regions (bytes)
#define SCR_BASE  67108864u
#define SCR_STRIDE 524288u
#define A5OFF     262144u
#define FIN_BASE  134217728u
#define FIN2_BASE 134742016u

#if !defined(__CUDA_ARCH__) || defined(__CUDA_ARCH_FEAT_SM103_ALL) || \
    (defined(__CUDA_ARCH_SPECIFIC__) && (__CUDA_ARCH_SPECIFIC__ == 1030))
#define HAS_TCGEN05 1
#else
#define HAS_TCGEN05 0
#endif

// ---- SMEM frame ----
#define SM_B     0
#define SM_BLO   65536
#define SM_A     131072
#define SM_HDR   229376
#define SM_TMEMP (SM_HDR + 0)
#define SM_FULL(s)  (SM_HDR + 16 + (s) * 8)
#define SM_EMPTY(s) (SM_HDR + 48 + (s) * 8)
#define SM_EPI(p)   (SM_HDR + 80 + (p) * 8)     // 4 slots
#define SM_EPID(p)  (SM_HDR + 112 + (p) * 8)    // 4 slots
#define SM_BIAS  (SM_HDR + 160)
#define DYN_SMEM 231424

#define IDESC_N128 0x8200490u
#define IDESC_N256 0x8400490u

__device__ uint4 g_tree[8650752];
__device__ int   g_flags[1024];
__device__ float g_EL[VOCABPAD * 128];
__device__ float g_ER[VOCABPAD * 128];

// ---------------- PTX helpers ----------------
__device__ __forceinline__ uint32_t smem_u32(const void* p) {
    uint32_t a;
    asm("{ .reg .u64 t; cvta.to.shared.u64 t, %1; cvt.u32.u64 %0, t; }" : "=r"(a) : "l"(p));
    return a;
}
__device__ __forceinline__ bool elect_one() {
    uint32_t pred;
    asm volatile("{ .reg .pred p; elect.sync _|p, 0xFFFFFFFF; selp.b32 %0, 1, 0, p; }" : "=r"(pred));
    return pred != 0;
}
__device__ __forceinline__ void sts128(uint32_t a, uint32_t x, uint32_t y, uint32_t z, uint32_t w) {
    asm volatile("st.shared.v4.b32 [%0], {%1,%2,%3,%4};" :: "r"(a), "r"(x), "r"(y), "r"(z), "r"(w) : "memory");
}
__device__ __forceinline__ int lds_s32(uint32_t a) {
    int v; asm volatile("ld.shared.b32 %0, [%1];" : "=r"(v) : "r"(a)); return v;
}
__device__ __forceinline__ float4 lds_f32x4(uint32_t a) {
    float4 v;
    asm volatile("ld.shared.v4.f32 {%0,%1,%2,%3}, [%4];"
                 : "=f"(v.x), "=f"(v.y), "=f"(v.z), "=f"(v.w) : "r"(a));
    return v;
}
__device__ __forceinline__ void sts_b32(uint32_t a, uint32_t v) {
    asm volatile("st.shared.b32 [%0], %1;" :: "r"(a), "r"(v) : "memory");
}
__device__ __forceinline__ void mbar_init(uint32_t a, uint32_t c) {
    asm volatile("mbarrier.init.shared.b64 [%0], %1;" :: "r"(a), "r"(c) : "memory");
}
__device__ __forceinline__ void mbar_arrive(uint32_t a) {
    asm volatile("mbarrier.arrive.shared.b64 _, [%0];" :: "r"(a) : "memory");
}
__device__ __forceinline__ void mbar_expect_tx(uint32_t a, uint32_t bytes) {
    asm volatile("mbarrier.arrive.expect_tx.shared.b64 _, [%0], %1;" :: "r"(a), "r"(bytes) : "memory");
}
__device__ __forceinline__ void bulk_g2s(uint32_t dst, const char* src, uint32_t bytes, uint32_t mbar) {
    asm volatile("cp.async.bulk.shared::cluster.global.mbarrier::complete_tx::bytes [%0], [%1], %2, [%3];"
                 :: "r"(dst), "l"(src), "r"(bytes), "r"(mbar) : "memory");
}
__device__ __forceinline__ void fence_proxy_async_s() {
    asm volatile("fence.proxy.async.shared::cta;" ::: "memory");
}
__device__ __forceinline__ void fence_proxy_async_g() {
    asm volatile("fence.proxy.async;" ::: "memory");
}
__device__ __forceinline__ int ld_acq(const int* p) {
    int v; asm volatile("ld.acquire.gpu.global.b32 %0, [%1];" : "=r"(v) : "l"(p) : "memory");
    return v;
}
__device__ __forceinline__ void red_rel_add1(int* p) {
    asm volatile("red.release.gpu.global.add.s32 [%0], 1;" :: "l"(p) : "memory");
}
__device__ __forceinline__ void nsleep() { asm volatile("nanosleep.u32 64;" ::: ); }

#if HAS_TCGEN05
__device__ __forceinline__ void mbar_wait(uint32_t a, uint32_t parity) {
    asm volatile(
        "{\n\t.reg .pred P;\n\t"
        "W%=:\n\t"
        "mbarrier.try_wait.parity.acquire.cta.shared::cta.b64 P, [%0], %1, 0x989680;\n\t"
        "@P bra.uni D%=;\n\t"
        "bra.uni W%=;\n\t"
        "D%=:\n\t}"
        :: "r"(a), "r"(parity) : "memory");
}
__device__ __forceinline__ void tmem_alloc(uint32_t dst, uint32_t n) {
    asm volatile("tcgen05.alloc.cta_group::1.sync.aligned.shared::cta.b32 [%0], %1;"
                 :: "r"(dst), "r"(n) : "memory");
}
__device__ __forceinline__ void tmem_relinquish() {
    asm volatile("tcgen05.relinquish_alloc_permit.cta_group::1.sync.aligned;");
}
__device__ __forceinline__ void tmem_dealloc(uint32_t t, uint32_t n) {
    asm volatile("tcgen05.dealloc.cta_group::1.sync.aligned.b32 %0, %1;" :: "r"(t), "r"(n));
}
__device__ __forceinline__ void mma_f16_ss(uint32_t d, uint64_t ad, uint64_t bd, uint32_t idesc, uint32_t en) {
    asm volatile(
        "{\n\t.reg .pred p;\n\tsetp.ne.u32 p, %4, 0;\n\t"
        "tcgen05.mma.cta_group::1.kind::f16 [%0], %1, %2, %3, {%5,%5,%5,%5}, p;\n\t}"
        :: "r"(d), "l"(ad), "l"(bd), "r"(idesc), "r"(en), "r"(0u) : "memory");
}
__device__ __forceinline__ void mma_commit(uint32_t mbar) {
    asm volatile("tcgen05.commit.cta_group::1.mbarrier::arrive::one.shared::cluster.b64 [%0];"
                 :: "r"(mbar) : "memory");
}
__device__ __forceinline__ void fence_after()  { asm volatile("tcgen05.fence::after_thread_sync;"  ::: "memory"); }
__device__ __forceinline__ void fence_before() { asm volatile("tcgen05.fence::before_thread_sync;" ::: "memory"); }
__device__ __forceinline__ void wait_ld()      { asm volatile("tcgen05.wait::ld.sync.aligned;"     ::: "memory"); }
__device__ __forceinline__ void ldtm32(uint32_t* r, uint32_t ta) {
    asm volatile(
        "tcgen05.ld.sync.aligned.32x32b.x32.b32 "
        "{%0, %1, %2, %3, %4, %5, %6, %7, "
        " %8, %9, %10, %11, %12, %13, %14, %15, "
        " %16, %17, %18, %19, %20, %21, %22, %23, "
        " %24, %25, %26, %27, %28, %29, %30, %31}, [%32];"
        : "=r"(r[0]), "=r"(r[1]), "=r"(r[2]), "=r"(r[3]),
          "=r"(r[4]), "=r"(r[5]), "=r"(r[6]), "=r"(r[7]),
          "=r"(r[8]), "=r"(r[9]), "=r"(r[10]), "=r"(r[11]),
          "=r"(r[12]), "=r"(r[13]), "=r"(r[14]), "=r"(r[15]),
          "=r"(r[16]), "=r"(r[17]), "=r"(r[18]), "=r"(r[19]),
          "=r"(r[20]), "=r"(r[21]), "=r"(r[22]), "=r"(r[23]),
          "=r"(r[24]), "=r"(r[25]), "=r"(r[26]), "=r"(r[27]),
          "=r"(r[28]), "=r"(r[29]), "=r"(r[30]), "=r"(r[31])
        : "r"(ta));
}
#endif // HAS_TCGEN05

__device__ __forceinline__ uint32_t swz(uint32_t off) { return off ^ ((off >> 3) & 0x70); }

__device__ __forceinline__ uint64_t mk_desc(uint32_t addr) {
    const uint64_t base = (uint64_t(2) << 61) | (uint64_t(1) << 46) |
                          (uint64_t(64) << 32) | (uint64_t(1) << 16);
    return base | ((uint64_t)(addr >> 4) & 0x3FFF);
}

// split 8 fp32 -> bf16 hi + exact-residual bf16 lo
__device__ __forceinline__ void split8(const float4& v0, const float4& v1, uint4& h, uint4& l) {
    float f[8] = {v0.x, v0.y, v0.z, v0.w, v1.x, v1.y, v1.z, v1.w};
    uint32_t hh[4], ll[4];
#pragma unroll
    for (int q = 0; q < 4; q++) {
        float a = f[2 * q], b = f[2 * q + 1];
        uint32_t hv;
        asm("cvt.rn.bf16x2.f32 %0, %1, %2;" : "=r"(hv) : "f"(b), "f"(a));
        hh[q] = hv;
        float ha = __uint_as_float(hv << 16);
        float hb = __uint_as_float(hv & 0xFFFF0000u);
        asm("cvt.rn.bf16x2.f32 %0, %1, %2;" : "=r"(ll[q]) : "f"(b - hb), "f"(a - ha));
    }
    h = make_uint4(hh[0], hh[1], hh[2], hh[3]);
    l = make_uint4(ll[0], ll[1], ll[2], ll[3]);
}

#if HAS_TCGEN05
// 12 split-MMAs for one K=64 chunk (A in ring stage s, B chunk c)
__device__ __forceinline__ void mma_chunk(uint32_t dA, uint32_t sb, int s, int c, bool first) {
    const uint32_t aHi = sb + SM_A + s * 32768;
    const uint64_t adh = mk_desc(aHi), adl = mk_desc(aHi + 16384);
    const uint64_t bdh = mk_desc(sb + SM_B + c * 16384);
    const uint64_t bdl = mk_desc(sb + SM_BLO + c * 16384);
#pragma unroll
    for (int ks = 0; ks < 4; ks++)
        mma_f16_ss(dA, adh + 2 * ks, bdh + 2 * ks, IDESC_N128, (!first || ks > 0) ? 1u : 0u);
#pragma unroll
    for (int ks = 0; ks < 4; ks++)
        mma_f16_ss(dA, adh + 2 * ks, bdl + 2 * ks, IDESC_N128, 1u);
#pragma unroll
    for (int ks = 0; ks < 4; ks++)
        mma_f16_ss(dA, adl + 2 * ks, bdh + 2 * ks, IDESC_N128, 1u);
}

// direct-SMEM compact A block at sb+SM_A
__device__ __forceinline__ void mma_chunk_direct(uint32_t dA, uint32_t sb, uint32_t half, int c, bool first) {
    const uint32_t b0 = sb + SM_A + (uint32_t)c * 2u * half;
    const uint64_t adh = mk_desc(b0), adl = mk_desc(b0 + half);
    const uint64_t bdh = mk_desc(sb + SM_B + c * 16384);
    const uint64_t bdl = mk_desc(sb + SM_BLO + c * 16384);
#pragma unroll
    for (int ks = 0; ks < 4; ks++)
        mma_f16_ss(dA, adh + 2 * ks, bdh + 2 * ks, IDESC_N128, (!first || ks > 0) ? 1u : 0u);
#pragma unroll
    for (int ks = 0; ks < 4; ks++)
        mma_f16_ss(dA, adh + 2 * ks, bdl + 2 * ks, IDESC_N128, 1u);
#pragma unroll
    for (int ks = 0; ks < 4; ks++)
        mma_f16_ss(dA, adl + 2 * ks, bdh + 2 * ks, IDESC_N128, 1u);
}

// fused12 epilogue: fixed 128-row consumer blocks (GMEM); qq range [qq0,qq0+qqn)
__device__ __forceinline__ void epi_store_chunked(uint32_t sb, uint32_t tmem, uint32_t dOff,
                                                  int tau, char* consBase, int q, int qq0, int qqn) {
    char* blkBase = consBase + (size_t)(tau >> 1) * BLKB;
    const int il = 64 * (tau & 1) + (q >> 1);
    const int cpar = 2 * (q & 1);
    for (int j = 0; j < qqn; j++) {
        const int qq = qq0 + j;
        uint32_t d[32];
        ldtm32(d, tmem + dOff + qq * 32);
        wait_ld();
        char* cb = blkBase + (size_t)(cpar + (qq >> 1)) * CHB;
#pragma unroll
        for (int u = 0; u < 4; u++) {
            float4 bv0 = lds_f32x4(sb + SM_BIAS + (qq * 32 + u * 8) * 4);
            float4 bv1 = lds_f32x4(sb + SM_BIAS + (qq * 32 + u * 8 + 4) * 4);
            float4 v0, v1;
            v0.x = __uint_as_float(d[8*u+0]) + bv0.x; v0.y = __uint_as_float(d[8*u+1]) + bv0.y;
            v0.z = __uint_as_float(d[8*u+2]) + bv0.z; v0.w = __uint_as_float(d[8*u+3]) + bv0.w;
            v1.x = __uint_as_float(d[8*u+4]) + bv1.x; v1.y = __uint_as_float(d[8*u+5]) + bv1.y;
            v1.z = __uint_as_float(d[8*u+6]) + bv1.z; v1.w = __uint_as_float(d[8*u+7]) + bv1.w;
            uint4 h, l; split8(v0, v1, h, l);
            const uint32_t off = swz((uint32_t)il * 128 + (32 * (qq & 1) + 8 * u) * 2);
            *(uint4*)(cb + off) = h;
            *(uint4*)(cb + 16384 + off) = l;
        }
    }
}

// generalized epilogue store to GMEM block (warp skip when slice invalid)
__device__ __forceinline__ void epi_store2(uint32_t sb, uint32_t tmem, uint32_t dOff, int V,
                                           char* dst, uint32_t dArB, int ilBase, int q, int qq0, int qqn) {
    if ((q & ~31) >= V) return;
    const uint32_t chbd = 2 * dArB;
    for (int j = 0; j < qqn; j++) {
        const int qq = qq0 + j;
        uint32_t d[32];
        ldtm32(d, tmem + dOff + qq * 32);
        wait_ld();
        if (q < V) {
            const int il = ilBase + (q >> 1);
            char* cb = dst + (size_t)(2 * (q & 1) + (qq >> 1)) * chbd;
#pragma unroll
            for (int u = 0; u < 4; u++) {
                float4 bv0 = lds_f32x4(sb + SM_BIAS + (qq * 32 + u * 8) * 4);
                float4 bv1 = lds_f32x4(sb + SM_BIAS + (qq * 32 + u * 8 + 4) * 4);
                float4 v0, v1;
                v0.x = __uint_as_float(d[8*u+0]) + bv0.x; v0.y = __uint_as_float(d[8*u+1]) + bv0.y;
                v0.z = __uint_as_float(d[8*u+2]) + bv0.z; v0.w = __uint_as_float(d[8*u+3]) + bv0.w;
                v1.x = __uint_as_float(d[8*u+4]) + bv1.x; v1.y = __uint_as_float(d[8*u+5]) + bv1.y;
                v1.z = __uint_as_float(d[8*u+6]) + bv1.z; v1.w = __uint_as_float(d[8*u+7]) + bv1.w;
                uint4 h, l; split8(v0, v1, h, l);
                const uint32_t off = swz((uint32_t)il * 128 + (32 * (qq & 1) + 8 * u) * 2);
                *(uint4*)(cb + off) = h;
                *(uint4*)(cb + dArB + off) = l;
            }
        }
    }
}

// epilogue store into SMEM compact block (warp skip when slice invalid)
__device__ __forceinline__ void epi_store2_smem(uint32_t sb, uint32_t tmem, uint32_t dOff, int V,
                                                uint32_t dstBase, uint32_t dArB, int q, int qq0, int qqn) {
    if ((q & ~31) >= V) return;
    const uint32_t chbd = 2 * dArB;
    for (int j = 0; j < qqn; j++) {
        const int qq = qq0 + j;
        uint32_t d[32];
        ldtm32(d, tmem + dOff + qq * 32);
        wait_ld();
        if (q < V) {
            const int il = q >> 1;
            uint32_t cb = dstBase + (uint32_t)(2 * (q & 1) + (qq >> 1)) * chbd;
#pragma unroll
            for (int u = 0; u < 4; u++) {
                float4 bv0 = lds_f32x4(sb + SM_BIAS + (qq * 32 + u * 8) * 4);
                float4 bv1 = lds_f32x4(sb + SM_BIAS + (qq * 32 + u * 8 + 4) * 4);
                float4 v0, v1;
                v0.x = __uint_as_float(d[8*u+0]) + bv0.x; v0.y = __uint_as_float(d[8*u+1]) + bv0.y;
                v0.z = __uint_as_float(d[8*u+2]) + bv0.z; v0.w = __uint_as_float(d[8*u+3]) + bv0.w;
                v1.x = __uint_as_float(d[8*u+4]) + bv1.x; v1.y = __uint_as_float(d[8*u+5]) + bv1.y;
                v1.z = __uint_as_float(d[8*u+6]) + bv1.z; v1.w = __uint_as_float(d[8*u+7]) + bv1.w;
                uint4 h, l; split8(v0, v1, h, l);
                const uint32_t off = swz((uint32_t)il * 128 + (32 * (qq & 1) + 8 * u) * 2);
                sts128(cb + off, h.x, h.y, h.z, h.w);
                sts128(cb + dArB + off, l.x, l.y, l.z, l.w);
            }
        }
    }
}
#endif

// ---------------------------------------------------------------------------
__global__ void clear_flags_k() {
    int i = blockIdx.x * 256 + threadIdx.x;
    if (i < 1024) g_flags[i] = 0;
}

// ---------------------------------------------------------------------------
// Precompute: EL/ER. Producers warps 0-8 (288, pipelined); epi warps 9-12;
// MMA warp 13.  (unchanged from R12)
// ---------------------------------------------------------------------------
__global__ __launch_bounds__(NT_PF, 1)
void precompute_tc(const float* __restrict__ emb, const float* __restrict__ W,
                   float* __restrict__ EL, float* __restrict__ ER, int numTiles)
{
#if HAS_TCGEN05
    extern __shared__ char dsm[];
    const uint32_t sb = (smem_u32(dsm) + 1023) & ~1023u;
    const int tid = threadIdx.x, wid = tid >> 5, lid = tid & 31;

    if (tid == 0) {
#pragma unroll
        for (int s = 0; s < NSTAGE; s++) { mbar_init(SM_FULL(s) + sb, NPROD); mbar_init(SM_EMPTY(s) + sb, 1); }
#pragma unroll
        for (int p = 0; p < 2; p++) { mbar_init(SM_EPI(p) + sb, 1); mbar_init(SM_EPID(p) + sb, 128); }
    }
    if (tid < 256) {
        const int n = tid;
        const float* wrow = W + (size_t)(n & 127) * KDIM + (n >> 7) * 128;
#pragma unroll
        for (int g = 0; g < 16; g++) {
            int k0 = g * 8;
            float4 v0 = *(const float4*)(wrow + k0);
            float4 v1 = *(const float4*)(wrow + k0 + 4);
            uint4 h, l; split8(v0, v1, h, l);
            uint32_t off = (k0 >> 6) * 32768 + swz(n * 128 + (k0 & 63) * 2);
            sts128(sb + SM_B + off, h.x, h.y, h.z, h.w);
            sts128(sb + SM_BLO + off, l.x, l.y, l.z, l.w);
        }
    }
    fence_proxy_async_s();
    __syncthreads();
    if (wid == 0) { tmem_alloc(sb + SM_TMEMP, 512); tmem_relinquish(); }
    __syncthreads();
    const uint32_t tmem = (uint32_t)lds_s32(sb + SM_TMEMP);

    const bool mmaLead = (wid == 13) && elect_one();
    int uc[NSTAGE] = {0, 0, 0}, fc[NSTAGE] = {0, 0, 0}, tp[2] = {0, 0}, epc[2] = {0, 0};
    int tl = 0, prevRow = 0;

    for (int tile = blockIdx.x; tile < numTiles; tile += gridDim.x) {
        const int tileRow = tile * TILE_M;
        if (tid < NPROD) {
#pragma unroll
            for (int c = 0; c < 2; c++) {
                const int s = (tl * 2 + c) % NSTAGE;
                const uint32_t hiB = sb + SM_A + s * 32768, loB = hiB + 16384;

                int i0 = tid;
                int er0 = tileRow + (i0 >> 3); if (er0 > VOCAB - 1) er0 = VOCAB - 1;
                const float* s0 = emb + (size_t)er0 * DDIM + c * 64 + (i0 & 7) * 8;
                float4 v0 = *(const float4*)s0;
                float4 v1 = *(const float4*)(s0 + 4);
                int i1 = i0 + NPROD;

                if (uc[s] > 0) mbar_wait(sb + SM_EMPTY(s), (uc[s] - 1) & 1);
                uc[s]++;

                while (true) {
                    float4 nv0, nv1;
                    if (i1 < 1024) {
                        int er1 = tileRow + (i1 >> 3); if (er1 > VOCAB - 1) er1 = VOCAB - 1;
                        const float* s1 = emb + (size_t)er1 * DDIM + c * 64 + (i1 & 7) * 8;
                        nv0 = *(const float4*)s1;
                        nv1 = *(const float4*)(s1 + 4);
                    }
                    uint4 h, l; split8(v0, v1, h, l);
                    const uint32_t off = swz((i0 >> 3) * 128 + (i0 & 7) * 16);
                    sts128(hiB + off, h.x, h.y, h.z, h.w);
                    sts128(loB + off, l.x, l.y, l.z, l.w);
                    if (i1 >= 1024) break;
                    i0 = i1; v0 = nv0; v1 = nv1; i1 += NPROD;
                }
                fence_proxy_async_s();
                mbar_arrive(sb + SM_FULL(s));
            }
        } else if (mmaLead) {
            const int p = tl & 1;
            if (tp[p] > 0) mbar_wait(sb + SM_EPID(p), (tp[p] - 1) & 1);
            tp[p]++;
            const uint32_t dA = tmem + p * 256;
#pragma unroll
            for (int c = 0; c < 2; c++) {
                const int s = (tl * 2 + c) % NSTAGE;
                mbar_wait(sb + SM_FULL(s), fc[s] & 1); fc[s]++;
                const uint32_t aHi = sb + SM_A + s * 32768;
                const uint64_t adh = mk_desc(aHi), adl = mk_desc(aHi + 16384);
                const uint64_t bdh = mk_desc(sb + SM_B + c * 32768);
                const uint64_t bdl = mk_desc(sb + SM_BLO + c * 32768);
#pragma unroll
                for (int ks = 0; ks < 4; ks++)
                    mma_f16_ss(dA, adh + 2 * ks, bdh + 2 * ks, IDESC_N256, (c > 0 || ks > 0) ? 1u : 0u);
#pragma unroll
                for (int ks = 0; ks < 4; ks++)
                    mma_f16_ss(dA, adh + 2 * ks, bdl + 2 * ks, IDESC_N256, 1u);
#pragma unroll
                for (int ks = 0; ks < 4; ks++)
                    mma_f16_ss(dA, adl + 2 * ks, bdh + 2 * ks, IDESC_N256, 1u);
                mma_commit(sb + SM_EMPTY(s));
            }
            mma_commit(sb + SM_EPI(p));
        } else if (wid >= 9 && wid <= 12 && tl >= 1) {
            const int p = (tl - 1) & 1;
            mbar_wait(sb + SM_EPI(p), epc[p] & 1); epc[p]++;
            fence_after();
            const int rowg = prevRow + (wid & 3) * 32 + lid;
#pragma unroll
            for (int q = 0; q < 8; q++) {
                uint32_t d[32];
                ldtm32(d, tmem + p * 256 + q * 32);
                wait_ld();
                const int col0 = q * 32;
                float* dst = (col0 < 128 ? EL + (size_t)rowg * DDIM + col0
                                         : ER + (size_t)rowg * DDIM + (col0 - 128));
#pragma unroll
                for (int u = 0; u < 8; u++)
                    *(float4*)(dst + u * 4) =
                        make_float4(__uint_as_float(d[4*u+0]), __uint_as_float(d[4*u+1]),
                                    __uint_as_float(d[4*u+2]), __uint_as_float(d[4*u+3]));
            }
            fence_before();
            mbar_arrive(sb + SM_EPID(p));
        }
        prevRow = tileRow; tl++;
    }

    if (wid >= 9 && wid <= 12 && tl >= 1) {
        const int p = (tl - 1) & 1;
        mbar_wait(sb + SM_EPI(p), epc[p] & 1); epc[p]++;
        fence_after();
        const int rowg = prevRow + (wid & 3) * 32 + lid;
#pragma unroll
        for (int q = 0; q < 8; q++) {
            uint32_t d[32];
            ldtm32(d, tmem + p * 256 + q * 32);
            wait_ld();
            const int col0 = q * 32;
            float* dst = (col0 < 128 ? EL + (size_t)rowg * DDIM + col0
                                     : ER + (size_t)rowg * DDIM + (col0 - 128));
#pragma unroll
            for (int u = 0; u < 8; u++)
                *(float4*)(dst + u * 4) =
                    make_float4(__uint_as_float(d[4*u+0]), __uint_as_float(d[4*u+1]),
                                __uint_as_float(d[4*u+2]), __uint_as_float(d[4*u+3]));
        }
        fence_before();
    }
    __syncthreads();
    if (wid == 0) tmem_dealloc(tmem, 512);
#else
    (void)emb; (void)W; (void)EL; (void)ER; (void)numTiles;
#endif
}

// ---------------------------------------------------------------------------
// Fused levels 1+2 (gather): producers warps 0-8; epi warps 9-12; MMA warp 13.
// NOW: 4 TMEM D-buffers (512 cols) for deeper MMA/epilogue pipelining.
// ---------------------------------------------------------------------------
__global__ __launch_bounds__(NT_PF, 1)
void fused12_tc(const int* __restrict__ ids,
                const float* __restrict__ EL, const float* __restrict__ ER,
                const float* __restrict__ W, const float* __restrict__ bias, int numTiles)
{
#if HAS_TCGEN05
    extern __shared__ char dsm[];
    const uint32_t sb = (smem_u32(dsm) + 1023) & ~1023u;
    const int tid = threadIdx.x, wid = tid >> 5, lid = tid & 31;
    char* arena = (char*)g_tree;

    if (tid == 0) {
#pragma unroll
        for (int s = 0; s < NSTAGE; s++) { mbar_init(SM_FULL(s) + sb, NPROD); mbar_init(SM_EMPTY(s) + sb, 1); }
#pragma unroll
        for (int p = 0; p < 4; p++) { mbar_init(SM_EPI(p) + sb, 1); mbar_init(SM_EPID(p) + sb, 128); }
    }
    if (tid < 128) sts_b32(sb + SM_BIAS + tid * 4, __float_as_uint(bias[tid]));

    if (tid < 256) {
        const int n = tid >> 1, h2 = tid & 1;
#pragma unroll
        for (int g = 0; g < 16; g++) {
            int k0 = h2 * 128 + g * 8;
            float4 v0 = *(const float4*)(W + (size_t)n * KDIM + k0);
            float4 v1 = *(const float4*)(W + (size_t)n * KDIM + k0 + 4);
            uint4 h, l; split8(v0, v1, h, l);
            uint32_t off = (k0 >> 6) * 16384 + swz(n * 128 + (k0 & 63) * 2);
            sts128(sb + SM_B + off, h.x, h.y, h.z, h.w);
            sts128(sb + SM_BLO + off, l.x, l.y, l.z, l.w);
        }
    }
    fence_proxy_async_s();
    __syncthreads();
    if (wid == 0) { tmem_alloc(sb + SM_TMEMP, 512); tmem_relinquish(); }
    __syncthreads();
    const uint32_t tmem = (uint32_t)lds_s32(sb + SM_TMEMP);

    const bool mmaLead = (wid == 13) && elect_one();
    int uc[NSTAGE] = {0, 0, 0}, fc[NSTAGE] = {0, 0, 0};
    int tp[4] = {0, 0, 0, 0}, epc[4] = {0, 0, 0, 0};
    int tl = 0, prevTile = 0;

    for (int tile = blockIdx.x; tile < numTiles; tile += gridDim.x) {
        const int tileRow = tile * TILE_M;
        if (tid < NPROD) {
#pragma unroll
            for (int c = 0; c < 4; c++) {
                const int s = (tl * 4 + c) % NSTAGE;
                const uint32_t hiB = sb + SM_A + s * 32768, loB = hiB + 16384;
                const int ch = c >> 1, sub0 = (c & 1) * 64;

                int i0 = tid;
                int2 id0 = *(const int2*)(ids + 2 * (2 * (tileRow + (i0 >> 3)) + ch));
                const float* pl0 = EL + (size_t)id0.x * DDIM + sub0 + (i0 & 7) * 8;
                const float* pr0 = ER + (size_t)id0.y * DDIM + sub0 + (i0 & 7) * 8;
                float4 l0 = *(const float4*)pl0,       l1 = *(const float4*)(pl0 + 4);
                float4 r0 = *(const float4*)pr0,       r1 = *(const float4*)(pr0 + 4);
                int i1 = i0 + NPROD;
                int2 id1;
                if (i1 < 1024)
                    id1 = *(const int2*)(ids + 2 * (2 * (tileRow + (i1 >> 3)) + ch));

                if (uc[s] > 0) mbar_wait(sb + SM_EMPTY(s), (uc[s] - 1) & 1);
                uc[s]++;

                while (true) {
                    float4 nl0, nl1, nr0, nr1;
                    if (i1 < 1024) {
                        const float* pl1 = EL + (size_t)id1.x * DDIM + sub0 + (i1 & 7) * 8;
                        const float* pr1 = ER + (size_t)id1.y * DDIM + sub0 + (i1 & 7) * 8;
                        nl0 = *(const float4*)pl1; nl1 = *(const float4*)(pl1 + 4);
                        nr0 = *(const float4*)pr1; nr1 = *(const float4*)(pr1 + 4);
                    }
                    int i2 = i1 + NPROD;
                    int2 id2;
                    if (i2 < 1024)
                        id2 = *(const int2*)(ids + 2 * (2 * (tileRow + (i2 >> 3)) + ch));

                    {
                        const int sub = sub0 + (i0 & 7) * 8;
                        float4 b0 = lds_f32x4(sb + SM_BIAS + sub * 4);
                        float4 b1 = lds_f32x4(sb + SM_BIAS + (sub + 4) * 4);
                        float4 v0, v1;
                        v0.x = l0.x + r0.x + b0.x; v0.y = l0.y + r0.y + b0.y;
                        v0.z = l0.z + r0.z + b0.z; v0.w = l0.w + r0.w + b0.w;
                        v1.x = l1.x + r1.x + b1.x; v1.y = l1.y + r1.y + b1.y;
                        v1.z = l1.z + r1.z + b1.z; v1.w = l1.w + r1.w + b1.w;
                        uint4 h, l; split8(v0, v1, h, l);
                        const uint32_t off = swz((i0 >> 3) * 128 + (i0 & 7) * 16);
                        sts128(hiB + off, h.x, h.y, h.z, h.w);
                        sts128(loB + off, l.x, l.y, l.z, l.w);
                    }
                    if (i1 >= 1024) break;
                    i0 = i1; l0 = nl0; l1 = nl1; r0 = nr0; r1 = nr1;
                    id1 = id2; i1 = i2;
                }
                fence_proxy_async_s();
                mbar_arrive(sb + SM_FULL(s));
            }
        } else if (mmaLead) {
            const int p = tl & 3;
            if (tp[p] > 0) mbar_wait(sb + SM_EPID(p), (tp[p] - 1) & 1);
            tp[p]++;
            const uint32_t dA = tmem + p * 128;
#pragma unroll
            for (int c = 0; c < 4; c++) {
                const int s = (tl * 4 + c) % NSTAGE;
                mbar_wait(sb + SM_FULL(s), fc[s] & 1); fc[s]++;
                mma_chunk(dA, sb, s, c, c == 0);
                mma_commit(sb + SM_EMPTY(s));
            }
            mma_commit(sb + SM_EPI(p));
        } else if (wid >= 9 && wid <= 12 && tl >= 1) {
            const int p = (tl - 1) & 3;
            mbar_wait(sb + SM_EPI(p), epc[p] & 1); epc[p]++;
            fence_after();
            epi_store_chunked(sb, tmem, p * 128, prevTile, arena, (wid & 3) * 32 + lid, 0, 4);
            fence_before();
            fence_proxy_async_g();
            mbar_arrive(sb + SM_EPID(p));
        }
        prevTile = tile; tl++;
    }

    if (wid >= 9 && wid <= 12 && tl >= 1) {
        const int p = (tl - 1) & 3;
        mbar_wait(sb + SM_EPI(p), epc[p] & 1); epc[p]++;
        fence_after();
        epi_store_chunked(sb, tmem, p * 128, prevTile, arena, (wid & 3) * 32 + lid, 0, 4);
        fence_before();
        fence_proxy_async_g();
    }
    __syncthreads();
    if (wid == 0) tmem_dealloc(tmem, 512);
#else
    (void)ids; (void)EL; (void)ER; (void)W; (void)bias; (void)numTiles;
#endif
}

// ---------------------------------------------------------------------------
// Tree kernel: 128 CTAs local cascade; 8 epilogue warps (column-split) to
// halve the serial epi latency; issuer warp 8; gemms 7-10 direct-SMEM A.
// ---------------------------------------------------------------------------
__global__ __launch_bounds__(NT_TREE, 1)
void tree2_tc(const float* __restrict__ W, const float* __restrict__ bias,
              float* __restrict__ out)
{
#if HAS_TCGEN05
    extern __shared__ char dsm[];
    const uint32_t sb = (smem_u32(dsm) + 1023) & ~1023u;
    const int tid = threadIdx.x, wid = tid >> 5, lid = tid & 31;
    const int bid = blockIdx.x;
    char* arena = (char*)g_tree;
    char* S    = arena + SCR_BASE + (size_t)bid * SCR_STRIDE;
    char* FIN  = arena + FIN_BASE;
    char* FIN2 = arena + FIN2_BASE;

    if (tid == 0) {
#pragma unroll
        for (int s = 0; s < NSTAGE; s++) { mbar_init(SM_FULL(s) + sb, 1); mbar_init(SM_EMPTY(s) + sb, 1); }
#pragma unroll
        for (int p = 0; p < 2; p++) { mbar_init(SM_EPI(p) + sb, 1); mbar_init(SM_EPID(p) + sb, 256); }
    }
    if (tid < 128) sts_b32(sb + SM_BIAS + tid * 4, __float_as_uint(bias[tid]));

    {   // B = W chunks
        const int n = tid >> 1, h2 = tid & 1;
        if (tid < 256) {
#pragma unroll
            for (int g = 0; g < 16; g++) {
                int k0 = h2 * 128 + g * 8;
                float4 v0 = *(const float4*)(W + (size_t)n * KDIM + k0);
                float4 v1 = *(const float4*)(W + (size_t)n * KDIM + k0 + 4);
                uint4 h, l; split8(v0, v1, h, l);
                uint32_t off = (k0 >> 6) * 16384 + swz(n * 128 + (k0 & 63) * 2);
                sts128(sb + SM_B + off, h.x, h.y, h.z, h.w);
                sts128(sb + SM_BLO + off, l.x, l.y, l.z, l.w);
            }
        }
    }
    fence_proxy_async_s();
    __syncthreads();
    if (wid == 0) { tmem_alloc(sb + SM_TMEMP, 256); tmem_relinquish(); }
    __syncthreads();
    const uint32_t tmem = (uint32_t)lds_s32(sb + SM_TMEMP);

    const int nG = 11 + (bid < 4 ? 1 : 0) + (bid < 2 ? 1 : 0);

    if (wid == 8 && elect_one()) {
        int kChunk = 0;
        int issued[NSTAGE] = {0, 0, 0}, fcons[NSTAGE] = {0, 0, 0};
        int epidW[2] = {0, 0};
        int epiSeen = -1;
        auto waitEpi = [&](int e) {
            while (epiSeen < e) {
                epiSeen++;
                const int pp = epiSeen & 1;
                mbar_wait(sb + SM_EPID(pp), epidW[pp] & 1);
                epidW[pp]++;
            }
        };
        auto issueChunk = [&](int k, const char* src, uint32_t half, int c) {
            const int s = k % NSTAGE;
            if (issued[s] > 0) mbar_wait(sb + SM_EMPTY(s), (issued[s] - 1) & 1);
            issued[s]++;
            mbar_expect_tx(sb + SM_FULL(s), 2 * half);
            bulk_g2s(sb + SM_A + s * 32768,         src + (size_t)c * 2 * half,        half, sb + SM_FULL(s));
            bulk_g2s(sb + SM_A + s * 32768 + 16384, src + (size_t)c * 2 * half + half, half, sb + SM_FULL(s));
        };

        for (int g = 0; g < nG; g++) {
            const int p = g & 1;
            const uint32_t dA = tmem + p * 128;

            if (g >= 7 && g <= 10) {
                waitEpi(g - 1);
                const uint32_t half = (g == 7) ? 8192u : (g == 8) ? 4096u : (g == 9) ? 2048u : 1024u;
#pragma unroll
                for (int c = 0; c < 4; c++)
                    mma_chunk_direct(dA, sb, half, c, c == 0);
            } else {
                if (g == 4) waitEpi(1);
                else if (g == 5) waitEpi(3);
                else if (g == 6) waitEpi(5);
                if (g == 11) { while (ld_acq(&g_flags[0]) < 16384) nsleep(); }
                if (g == 12) { while (ld_acq(&g_flags[1]) < 512)   nsleep(); }

                const char* src; uint32_t half = 16384;
                if (g < 4)       src = arena + (size_t)(4 * bid + g) * BLKB;
                else if (g == 4) src = S;
                else if (g == 5) src = S + BLKB;
                else if (g == 6) src = S + A5OFF;
                else if (g == 11) src = FIN + (size_t)bid * BLKB;
                else              src = FIN2 + (size_t)bid * BLKB;

                issueChunk(kChunk + 0, src, half, 0);
                issueChunk(kChunk + 1, src, half, 1);
                issueChunk(kChunk + 2, src, half, 2);

                if (g == 2 || g == 3) waitEpi(g - 2);
                else if (g == 4) waitEpi(2);
                else if (g >= 11) waitEpi(g - 1);

                { const int s = kChunk % NSTAGE;
                  mbar_wait(sb + SM_FULL(s), fcons[s] & 1); fcons[s]++;
                  mma_chunk(dA, sb, s, 0, true);
                  mma_commit(sb + SM_EMPTY(s)); }
                issueChunk(kChunk + 3, src, half, 3);
#pragma unroll
                for (int c = 1; c < 4; c++) {
                    const int s = (kChunk + c) % NSTAGE;
                    mbar_wait(sb + SM_FULL(s), fcons[s] & 1); fcons[s]++;
                    mma_chunk(dA, sb, s, c, false);
                    mma_commit(sb + SM_EMPTY(s));
                }
                kChunk += 4;
            }
            mma_commit(sb + SM_EPI(p));
        }
    } else if (wid < 8) {
        int epc[2] = {0, 0};
        const int q = (wid & 3) * 32 + lid;   // row in tile
        const int qq0 = (wid >> 2) * 2;       // column half: qq in {qq0, qq0+1}
        for (int e = 0; e < nG; e++) {
            const int p = e & 1;
            mbar_wait(sb + SM_EPI(p), epc[p] & 1); epc[p]++;
            fence_after();
            if (e == 12) {
                float* op = out + (size_t)(128 * bid + q) * DDIM;
                for (int j = 0; j < 2; j++) {
                    const int qq = qq0 + j;
                    uint32_t d[32];
                    ldtm32(d, tmem + p * 128 + qq * 32);
                    wait_ld();
#pragma unroll
                    for (int u = 0; u < 8; u++) {
                        float4 bv = lds_f32x4(sb + SM_BIAS + (qq * 32 + u * 4) * 4);
                        *(float4*)(op + qq * 32 + u * 4) =
                            make_float4(__uint_as_float(d[4*u+0]) + bv.x, __uint_as_float(d[4*u+1]) + bv.y,
                                        __uint_as_float(d[4*u+2]) + bv.z, __uint_as_float(d[4*u+3]) + bv.w);
                    }
                }
                fence_before();
            } else if (e >= 6 && e <= 9) {
                const uint32_t dArB = (e == 6) ? 8192u : (e == 7) ? 4096u : (e == 8) ? 2048u : 1024u;
                const int V = (e == 6) ? 128 : (e == 7) ? 64 : (e == 8) ? 32 : 16;
                epi_store2_smem(sb, tmem, p * 128, V, sb + SM_A, dArB, q, qq0, 2);
                fence_before();
                fence_proxy_async_s();
            } else {
                int V, ilBase; char* dst; uint32_t dArB = 16384;
                if (e < 6)       { V = 128; dst = S + (size_t)(e >> 1) * BLKB; ilBase = 64 * (e & 1); }
                else if (e == 10){ V = 8;   dst = FIN + (size_t)(bid >> 5) * BLKB; ilBase = 4 * (bid & 31); }
                else             { V = 128; dst = FIN2 + (size_t)(bid >> 1) * BLKB; ilBase = 64 * (bid & 1); }
                epi_store2(sb, tmem, p * 128, V, dst, dArB, ilBase, q, qq0, 2);
                fence_before();
                fence_proxy_async_g();
                if (e == 10 && qq0 == 0) red_rel_add1(&g_flags[0]);
                if (e == 11 && qq0 == 0) red_rel_add1(&g_flags[1]);
            }
            mbar_arrive(sb + SM_EPID(p));
        }
    }
    __syncthreads();
    if (wid == 0) tmem_dealloc(tmem, 256);
#else
    (void)W; (void)bias; (void)out;
#endif
}

// ---------------------------------------------------------------------------
extern "C" void kernel_launch(void* const* d_in, const int* in_sizes, int n_in,
                              void* d_out, int out_size)
{
    (void)in_sizes; (void)n_in; (void)out_size;
    const int*   ids  = (const int*)d_in[0];
    const float* emb  = (const float*)d_in[1];
    const float* W    = (const float*)d_in[2];
    const float* bias = (const float*)d_in[3];
    float* out = (float*)d_out;

    static bool attr_set = false;
    if (!attr_set) {
        cudaFuncSetAttribute(precompute_tc, cudaFuncAttributeMaxDynamicSharedMemorySize, DYN_SMEM);
        cudaFuncSetAttribute(fused12_tc,    cudaFuncAttributeMaxDynamicSharedMemorySize, DYN_SMEM);
        cudaFuncSetAttribute(tree2_tc,      cudaFuncAttributeMaxDynamicSharedMemorySize, DYN_SMEM);
        attr_set = true;
    }

    float *elp, *erp;
    cudaGetSymbolAddress((void**)&elp, g_EL);
    cudaGetSymbolAddress((void**)&erp, g_ER);

    clear_flags_k<<<4, 256>>>();
    precompute_tc<<<148, NT_PF, DYN_SMEM>>>(emb, W, elp, erp, VOCABPAD / TILE_M);
    fused12_tc<<<148, NT_PF, DYN_SMEM>>>(ids, elp, erp, W, bias, 1024);
    tree2_tc<<<128, NT_TREE, DYN_SMEM>>>(W, bias, out);
}

// round 16
// speedup vs baseline: 1.3948x; 1.0603x over previous
#include <cuda_runtime.h>
#include <cstdint>

#define VOCAB    100000
#define VOCABPAD 100096
#define DDIM     128
#define KDIM     256
#define NT_PF    448                    // 9 prod + 4 epi + 1 mma warps
#define NT_TREE  256
#define NPROD    288                    // warps 0-8 produce
#define TILE_M   128
#define NSTAGE   3

#define BLKB     131072u
#define CHB      32768u

// arena regions (bytes)
#define SCR_BASE  67108864u
#define SCR_STRIDE 524288u
#define A5OFF     262144u
#define FIN_BASE  134217728u
#define FIN2_BASE 134742016u

#if !defined(__CUDA_ARCH__) || defined(__CUDA_ARCH_FEAT_SM103_ALL) || \
    (defined(__CUDA_ARCH_SPECIFIC__) && (__CUDA_ARCH_SPECIFIC__ == 1030))
#define HAS_TCGEN05 1
#else
#define HAS_TCGEN05 0
#endif

// ---- SMEM frame ----
#define SM_B     0
#define SM_BLO   65536
#define SM_A     131072
#define SM_HDR   229376
#define SM_TMEMP (SM_HDR + 0)
#define SM_FULL(s)  (SM_HDR + 16 + (s) * 8)
#define SM_EMPTY(s) (SM_HDR + 48 + (s) * 8)
#define SM_EPI(p)   (SM_HDR + 80 + (p) * 8)
#define SM_EPID(p)  (SM_HDR + 96 + (p) * 8)
#define SM_BIAS  (SM_HDR + 128)
#define DYN_SMEM 231424

#define IDESC_N128 0x8200490u
#define IDESC_N256 0x8400490u

__device__ uint4 g_tree[8650752];
__device__ int   g_flags[1024];
__device__ float g_EL[VOCABPAD * 128];
__device__ float g_ER[VOCABPAD * 128];

// ---------------- PTX helpers ----------------
__device__ __forceinline__ uint32_t smem_u32(const void* p) {
    uint32_t a;
    asm("{ .reg .u64 t; cvta.to.shared.u64 t, %1; cvt.u32.u64 %0, t; }" : "=r"(a) : "l"(p));
    return a;
}
__device__ __forceinline__ bool elect_one() {
    uint32_t pred;
    asm volatile("{ .reg .pred p; elect.sync _|p, 0xFFFFFFFF; selp.b32 %0, 1, 0, p; }" : "=r"(pred));
    return pred != 0;
}
__device__ __forceinline__ void sts128(uint32_t a, uint32_t x, uint32_t y, uint32_t z, uint32_t w) {
    asm volatile("st.shared.v4.b32 [%0], {%1,%2,%3,%4};" :: "r"(a), "r"(x), "r"(y), "r"(z), "r"(w) : "memory");
}
__device__ __forceinline__ int lds_s32(uint32_t a) {
    int v; asm volatile("ld.shared.b32 %0, [%1];" : "=r"(v) : "r"(a)); return v;
}
__device__ __forceinline__ float4 lds_f32x4(uint32_t a) {
    float4 v;
    asm volatile("ld.shared.v4.f32 {%0,%1,%2,%3}, [%4];"
                 : "=f"(v.x), "=f"(v.y), "=f"(v.z), "=f"(v.w) : "r"(a));
    return v;
}
__device__ __forceinline__ void sts_b32(uint32_t a, uint32_t v) {
    asm volatile("st.shared.b32 [%0], %1;" :: "r"(a), "r"(v) : "memory");
}
__device__ __forceinline__ void mbar_init(uint32_t a, uint32_t c) {
    asm volatile("mbarrier.init.shared.b64 [%0], %1;" :: "r"(a), "r"(c) : "memory");
}
__device__ __forceinline__ void mbar_arrive(uint32_t a) {
    asm volatile("mbarrier.arrive.shared.b64 _, [%0];" :: "r"(a) : "memory");
}
__device__ __forceinline__ void mbar_expect_tx(uint32_t a, uint32_t bytes) {
    asm volatile("mbarrier.arrive.expect_tx.shared.b64 _, [%0], %1;" :: "r"(a), "r"(bytes) : "memory");
}
__device__ __forceinline__ void bulk_g2s(uint32_t dst, const char* src, uint32_t bytes, uint32_t mbar) {
    asm volatile("cp.async.bulk.shared::cluster.global.mbarrier::complete_tx::bytes [%0], [%1], %2, [%3];"
                 :: "r"(dst), "l"(src), "r"(bytes), "r"(mbar) : "memory");
}
__device__ __forceinline__ void fence_proxy_async_s() {
    asm volatile("fence.proxy.async.shared::cta;" ::: "memory");
}
__device__ __forceinline__ void fence_proxy_async_g() {
    asm volatile("fence.proxy.async;" ::: "memory");
}
__device__ __forceinline__ int ld_acq(const int* p) {
    int v; asm volatile("ld.acquire.gpu.global.b32 %0, [%1];" : "=r"(v) : "l"(p) : "memory");
    return v;
}
__device__ __forceinline__ void red_rel_add1(int* p) {
    asm volatile("red.release.gpu.global.add.s32 [%0], 1;" :: "l"(p) : "memory");
}
__device__ __forceinline__ void nsleep() { asm volatile("nanosleep.u32 64;" ::: ); }

#if HAS_TCGEN05
__device__ __forceinline__ void mbar_wait(uint32_t a, uint32_t parity) {
    asm volatile(
        "{\n\t.reg .pred P;\n\t"
        "W%=:\n\t"
        "mbarrier.try_wait.parity.acquire.cta.shared::cta.b64 P, [%0], %1, 0x989680;\n\t"
        "@P bra.uni D%=;\n\t"
        "bra.uni W%=;\n\t"
        "D%=:\n\t}"
        :: "r"(a), "r"(parity) : "memory");
}
__device__ __forceinline__ void tmem_alloc(uint32_t dst, uint32_t n) {
    asm volatile("tcgen05.alloc.cta_group::1.sync.aligned.shared::cta.b32 [%0], %1;"
                 :: "r"(dst), "r"(n) : "memory");
}
__device__ __forceinline__ void tmem_relinquish() {
    asm volatile("tcgen05.relinquish_alloc_permit.cta_group::1.sync.aligned;");
}
__device__ __forceinline__ void tmem_dealloc(uint32_t t, uint32_t n) {
    asm volatile("tcgen05.dealloc.cta_group::1.sync.aligned.b32 %0, %1;" :: "r"(t), "r"(n));
}
__device__ __forceinline__ void mma_f16_ss(uint32_t d, uint64_t ad, uint64_t bd, uint32_t idesc, uint32_t en) {
    asm volatile(
        "{\n\t.reg .pred p;\n\tsetp.ne.u32 p, %4, 0;\n\t"
        "tcgen05.mma.cta_group::1.kind::f16 [%0], %1, %2, %3, {%5,%5,%5,%5}, p;\n\t}"
        :: "r"(d), "l"(ad), "l"(bd), "r"(idesc), "r"(en), "r"(0u) : "memory");
}
__device__ __forceinline__ void mma_commit(uint32_t mbar) {
    asm volatile("tcgen05.commit.cta_group::1.mbarrier::arrive::one.shared::cluster.b64 [%0];"
                 :: "r"(mbar) : "memory");
}
__device__ __forceinline__ void fence_after()  { asm volatile("tcgen05.fence::after_thread_sync;"  ::: "memory"); }
__device__ __forceinline__ void fence_before() { asm volatile("tcgen05.fence::before_thread_sync;" ::: "memory"); }
__device__ __forceinline__ void wait_ld()      { asm volatile("tcgen05.wait::ld.sync.aligned;"     ::: "memory"); }
__device__ __forceinline__ void ldtm32(uint32_t* r, uint32_t ta) {
    asm volatile(
        "tcgen05.ld.sync.aligned.32x32b.x32.b32 "
        "{%0, %1, %2, %3, %4, %5, %6, %7, "
        " %8, %9, %10, %11, %12, %13, %14, %15, "
        " %16, %17, %18, %19, %20, %21, %22, %23, "
        " %24, %25, %26, %27, %28, %29, %30, %31}, [%32];"
        : "=r"(r[0]), "=r"(r[1]), "=r"(r[2]), "=r"(r[3]),
          "=r"(r[4]), "=r"(r[5]), "=r"(r[6]), "=r"(r[7]),
          "=r"(r[8]), "=r"(r[9]), "=r"(r[10]), "=r"(r[11]),
          "=r"(r[12]), "=r"(r[13]), "=r"(r[14]), "=r"(r[15]),
          "=r"(r[16]), "=r"(r[17]), "=r"(r[18]), "=r"(r[19]),
          "=r"(r[20]), "=r"(r[21]), "=r"(r[22]), "=r"(r[23]),
          "=r"(r[24]), "=r"(r[25]), "=r"(r[26]), "=r"(r[27]),
          "=r"(r[28]), "=r"(r[29]), "=r"(r[30]), "=r"(r[31])
        : "r"(ta));
}
#endif // HAS_TCGEN05

__device__ __forceinline__ uint32_t swz(uint32_t off) { return off ^ ((off >> 3) & 0x70); }

__device__ __forceinline__ uint64_t mk_desc(uint32_t addr) {
    const uint64_t base = (uint64_t(2) << 61) | (uint64_t(1) << 46) |
                          (uint64_t(64) << 32) | (uint64_t(1) << 16);
    return base | ((uint64_t)(addr >> 4) & 0x3FFF);
}

// split 8 fp32 -> bf16 hi + exact-residual bf16 lo
__device__ __forceinline__ void split8(const float4& v0, const float4& v1, uint4& h, uint4& l) {
    float f[8] = {v0.x, v0.y, v0.z, v0.w, v1.x, v1.y, v1.z, v1.w};
    uint32_t hh[4], ll[4];
#pragma unroll
    for (int q = 0; q < 4; q++) {
        float a = f[2 * q], b = f[2 * q + 1];
        uint32_t hv;
        asm("cvt.rn.bf16x2.f32 %0, %1, %2;" : "=r"(hv) : "f"(b), "f"(a));
        hh[q] = hv;
        float ha = __uint_as_float(hv << 16);
        float hb = __uint_as_float(hv & 0xFFFF0000u);
        asm("cvt.rn.bf16x2.f32 %0, %1, %2;" : "=r"(ll[q]) : "f"(b - hb), "f"(a - ha));
    }
    h = make_uint4(hh[0], hh[1], hh[2], hh[3]);
    l = make_uint4(ll[0], ll[1], ll[2], ll[3]);
}

#if HAS_TCGEN05
// 12 split-MMAs for one K=64 chunk (A in ring stage s, B chunk c)
__device__ __forceinline__ void mma_chunk(uint32_t dA, uint32_t sb, int s, int c, bool first) {
    const uint32_t aHi = sb + SM_A + s * 32768;
    const uint64_t adh = mk_desc(aHi), adl = mk_desc(aHi + 16384);
    const uint64_t bdh = mk_desc(sb + SM_B + c * 16384);
    const uint64_t bdl = mk_desc(sb + SM_BLO + c * 16384);
#pragma unroll
    for (int ks = 0; ks < 4; ks++)
        mma_f16_ss(dA, adh + 2 * ks, bdh + 2 * ks, IDESC_N128, (!first || ks > 0) ? 1u : 0u);
#pragma unroll
    for (int ks = 0; ks < 4; ks++)
        mma_f16_ss(dA, adh + 2 * ks, bdl + 2 * ks, IDESC_N128, 1u);
#pragma unroll
    for (int ks = 0; ks < 4; ks++)
        mma_f16_ss(dA, adl + 2 * ks, bdh + 2 * ks, IDESC_N128, 1u);
}

// direct-SMEM compact A block at sb+SM_A
__device__ __forceinline__ void mma_chunk_direct(uint32_t dA, uint32_t sb, uint32_t half, int c, bool first) {
    const uint32_t b0 = sb + SM_A + (uint32_t)c * 2u * half;
    const uint64_t adh = mk_desc(b0), adl = mk_desc(b0 + half);
    const uint64_t bdh = mk_desc(sb + SM_B + c * 16384);
    const uint64_t bdl = mk_desc(sb + SM_BLO + c * 16384);
#pragma unroll
    for (int ks = 0; ks < 4; ks++)
        mma_f16_ss(dA, adh + 2 * ks, bdh + 2 * ks, IDESC_N128, (!first || ks > 0) ? 1u : 0u);
#pragma unroll
    for (int ks = 0; ks < 4; ks++)
        mma_f16_ss(dA, adh + 2 * ks, bdl + 2 * ks, IDESC_N128, 1u);
#pragma unroll
    for (int ks = 0; ks < 4; ks++)
        mma_f16_ss(dA, adl + 2 * ks, bdh + 2 * ks, IDESC_N128, 1u);
}

// fused12 epilogue: fixed 128-row consumer blocks (GMEM)
__device__ __forceinline__ void epi_store_chunked(uint32_t sb, uint32_t tmem, int p,
                                                  int tau, char* consBase, int q) {
    char* blkBase = consBase + (size_t)(tau >> 1) * BLKB;
    const int il = 64 * (tau & 1) + (q >> 1);
    const int cpar = 2 * (q & 1);
#pragma unroll
    for (int qq = 0; qq < 4; qq++) {
        uint32_t d[32];
        ldtm32(d, tmem + p * 128 + qq * 32);
        wait_ld();
        char* cb = blkBase + (size_t)(cpar + (qq >> 1)) * CHB;
#pragma unroll
        for (int u = 0; u < 4; u++) {
            float4 bv0 = lds_f32x4(sb + SM_BIAS + (qq * 32 + u * 8) * 4);
            float4 bv1 = lds_f32x4(sb + SM_BIAS + (qq * 32 + u * 8 + 4) * 4);
            float4 v0, v1;
            v0.x = __uint_as_float(d[8*u+0]) + bv0.x; v0.y = __uint_as_float(d[8*u+1]) + bv0.y;
            v0.z = __uint_as_float(d[8*u+2]) + bv0.z; v0.w = __uint_as_float(d[8*u+3]) + bv0.w;
            v1.x = __uint_as_float(d[8*u+4]) + bv1.x; v1.y = __uint_as_float(d[8*u+5]) + bv1.y;
            v1.z = __uint_as_float(d[8*u+6]) + bv1.z; v1.w = __uint_as_float(d[8*u+7]) + bv1.w;
            uint4 h, l; split8(v0, v1, h, l);
            const uint32_t off = swz((uint32_t)il * 128 + (32 * (qq & 1) + 8 * u) * 2);
            *(uint4*)(cb + off) = h;
            *(uint4*)(cb + 16384 + off) = l;
        }
    }
}

// generalized epilogue store to GMEM block (whole-warp skip when slice invalid)
__device__ __forceinline__ void epi_store2(uint32_t sb, uint32_t tmem, int p, int V,
                                           char* dst, uint32_t dArB, int ilBase, int q) {
    if ((q & ~31) >= V) return;
    const uint32_t chbd = 2 * dArB;
#pragma unroll
    for (int qq = 0; qq < 4; qq++) {
        uint32_t d[32];
        ldtm32(d, tmem + p * 128 + qq * 32);
        wait_ld();
        if (q < V) {
            const int il = ilBase + (q >> 1);
            char* cb = dst + (size_t)(2 * (q & 1) + (qq >> 1)) * chbd;
#pragma unroll
            for (int u = 0; u < 4; u++) {
                float4 bv0 = lds_f32x4(sb + SM_BIAS + (qq * 32 + u * 8) * 4);
                float4 bv1 = lds_f32x4(sb + SM_BIAS + (qq * 32 + u * 8 + 4) * 4);
                float4 v0, v1;
                v0.x = __uint_as_float(d[8*u+0]) + bv0.x; v0.y = __uint_as_float(d[8*u+1]) + bv0.y;
                v0.z = __uint_as_float(d[8*u+2]) + bv0.z; v0.w = __uint_as_float(d[8*u+3]) + bv0.w;
                v1.x = __uint_as_float(d[8*u+4]) + bv1.x; v1.y = __uint_as_float(d[8*u+5]) + bv1.y;
                v1.z = __uint_as_float(d[8*u+6]) + bv1.z; v1.w = __uint_as_float(d[8*u+7]) + bv1.w;
                uint4 h, l; split8(v0, v1, h, l);
                const uint32_t off = swz((uint32_t)il * 128 + (32 * (qq & 1) + 8 * u) * 2);
                *(uint4*)(cb + off) = h;
                *(uint4*)(cb + dArB + off) = l;
            }
        }
    }
}

// epilogue store into SMEM compact block (whole-warp skip when slice invalid)
__device__ __forceinline__ void epi_store2_smem(uint32_t sb, uint32_t tmem, int p, int V,
                                                uint32_t dstBase, uint32_t dArB, int q) {
    if ((q & ~31) >= V) return;
    const uint32_t chbd = 2 * dArB;
#pragma unroll
    for (int qq = 0; qq < 4; qq++) {
        uint32_t d[32];
        ldtm32(d, tmem + p * 128 + qq * 32);
        wait_ld();
        if (q < V) {
            const int il = q >> 1;
            uint32_t cb = dstBase + (uint32_t)(2 * (q & 1) + (qq >> 1)) * chbd;
#pragma unroll
            for (int u = 0; u < 4; u++) {
                float4 bv0 = lds_f32x4(sb + SM_BIAS + (qq * 32 + u * 8) * 4);
                float4 bv1 = lds_f32x4(sb + SM_BIAS + (qq * 32 + u * 8 + 4) * 4);
                float4 v0, v1;
                v0.x = __uint_as_float(d[8*u+0]) + bv0.x; v0.y = __uint_as_float(d[8*u+1]) + bv0.y;
                v0.z = __uint_as_float(d[8*u+2]) + bv0.z; v0.w = __uint_as_float(d[8*u+3]) + bv0.w;
                v1.x = __uint_as_float(d[8*u+4]) + bv1.x; v1.y = __uint_as_float(d[8*u+5]) + bv1.y;
                v1.z = __uint_as_float(d[8*u+6]) + bv1.z; v1.w = __uint_as_float(d[8*u+7]) + bv1.w;
                uint4 h, l; split8(v0, v1, h, l);
                const uint32_t off = swz((uint32_t)il * 128 + (32 * (qq & 1) + 8 * u) * 2);
                sts128(cb + off, h.x, h.y, h.z, h.w);
                sts128(cb + dArB + off, l.x, l.y, l.z, l.w);
            }
        }
    }
}
#endif

// ---------------------------------------------------------------------------
__global__ void clear_flags_k() {
    int i = blockIdx.x * 256 + threadIdx.x;
    if (i < 1024) g_flags[i] = 0;
}

// ---------------------------------------------------------------------------
// Precompute: EL/ER. Producers warps 0-8 (288, pipelined); epi warps 9-12;
// MMA warp 13.  (R12, unchanged)
// ---------------------------------------------------------------------------
__global__ __launch_bounds__(NT_PF, 1)
void precompute_tc(const float* __restrict__ emb, const float* __restrict__ W,
                   float* __restrict__ EL, float* __restrict__ ER, int numTiles)
{
#if HAS_TCGEN05
    extern __shared__ char dsm[];
    const uint32_t sb = (smem_u32(dsm) + 1023) & ~1023u;
    const int tid = threadIdx.x, wid = tid >> 5, lid = tid & 31;

    if (tid == 0) {
#pragma unroll
        for (int s = 0; s < NSTAGE; s++) { mbar_init(SM_FULL(s) + sb, NPROD); mbar_init(SM_EMPTY(s) + sb, 1); }
#pragma unroll
        for (int p = 0; p < 2; p++) { mbar_init(SM_EPI(p) + sb, 1); mbar_init(SM_EPID(p) + sb, 128); }
    }
    if (tid < 256) {
        const int n = tid;
        const float* wrow = W + (size_t)(n & 127) * KDIM + (n >> 7) * 128;
#pragma unroll
        for (int g = 0; g < 16; g++) {
            int k0 = g * 8;
            float4 v0 = *(const float4*)(wrow + k0);
            float4 v1 = *(const float4*)(wrow + k0 + 4);
            uint4 h, l; split8(v0, v1, h, l);
            uint32_t off = (k0 >> 6) * 32768 + swz(n * 128 + (k0 & 63) * 2);
            sts128(sb + SM_B + off, h.x, h.y, h.z, h.w);
            sts128(sb + SM_BLO + off, l.x, l.y, l.z, l.w);
        }
    }
    fence_proxy_async_s();
    __syncthreads();
    if (wid == 0) { tmem_alloc(sb + SM_TMEMP, 512); tmem_relinquish(); }
    __syncthreads();
    const uint32_t tmem = (uint32_t)lds_s32(sb + SM_TMEMP);

    const bool mmaLead = (wid == 13) && elect_one();
    int uc[NSTAGE] = {0, 0, 0}, fc[NSTAGE] = {0, 0, 0}, tp[2] = {0, 0}, epc[2] = {0, 0};
    int tl = 0, prevRow = 0;

    for (int tile = blockIdx.x; tile < numTiles; tile += gridDim.x) {
        const int tileRow = tile * TILE_M;
        if (tid < NPROD) {
#pragma unroll
            for (int c = 0; c < 2; c++) {
                const int s = (tl * 2 + c) % NSTAGE;
                const uint32_t hiB = sb + SM_A + s * 32768, loB = hiB + 16384;

                int i0 = tid;
                int er0 = tileRow + (i0 >> 3); if (er0 > VOCAB - 1) er0 = VOCAB - 1;
                const float* s0 = emb + (size_t)er0 * DDIM + c * 64 + (i0 & 7) * 8;
                float4 v0 = *(const float4*)s0;
                float4 v1 = *(const float4*)(s0 + 4);
                int i1 = i0 + NPROD;

                if (uc[s] > 0) mbar_wait(sb + SM_EMPTY(s), (uc[s] - 1) & 1);
                uc[s]++;

                while (true) {
                    float4 nv0, nv1;
                    if (i1 < 1024) {
                        int er1 = tileRow + (i1 >> 3); if (er1 > VOCAB - 1) er1 = VOCAB - 1;
                        const float* s1 = emb + (size_t)er1 * DDIM + c * 64 + (i1 & 7) * 8;
                        nv0 = *(const float4*)s1;
                        nv1 = *(const float4*)(s1 + 4);
                    }
                    uint4 h, l; split8(v0, v1, h, l);
                    const uint32_t off = swz((i0 >> 3) * 128 + (i0 & 7) * 16);
                    sts128(hiB + off, h.x, h.y, h.z, h.w);
                    sts128(loB + off, l.x, l.y, l.z, l.w);
                    if (i1 >= 1024) break;
                    i0 = i1; v0 = nv0; v1 = nv1; i1 += NPROD;
                }
                fence_proxy_async_s();
                mbar_arrive(sb + SM_FULL(s));
            }
        } else if (mmaLead) {
            const int p = tl & 1;
            if (tp[p] > 0) mbar_wait(sb + SM_EPID(p), (tp[p] - 1) & 1);
            tp[p]++;
            const uint32_t dA = tmem + p * 256;
#pragma unroll
            for (int c = 0; c < 2; c++) {
                const int s = (tl * 2 + c) % NSTAGE;
                mbar_wait(sb + SM_FULL(s), fc[s] & 1); fc[s]++;
                const uint32_t aHi = sb + SM_A + s * 32768;
                const uint64_t adh = mk_desc(aHi), adl = mk_desc(aHi + 16384);
                const uint64_t bdh = mk_desc(sb + SM_B + c * 32768);
                const uint64_t bdl = mk_desc(sb + SM_BLO + c * 32768);
#pragma unroll
                for (int ks = 0; ks < 4; ks++)
                    mma_f16_ss(dA, adh + 2 * ks, bdh + 2 * ks, IDESC_N256, (c > 0 || ks > 0) ? 1u : 0u);
#pragma unroll
                for (int ks = 0; ks < 4; ks++)
                    mma_f16_ss(dA, adh + 2 * ks, bdl + 2 * ks, IDESC_N256, 1u);
#pragma unroll
                for (int ks = 0; ks < 4; ks++)
                    mma_f16_ss(dA, adl + 2 * ks, bdh + 2 * ks, IDESC_N256, 1u);
                mma_commit(sb + SM_EMPTY(s));
            }
            mma_commit(sb + SM_EPI(p));
        } else if (wid >= 9 && wid <= 12 && tl >= 1) {
            const int p = (tl - 1) & 1;
            mbar_wait(sb + SM_EPI(p), epc[p] & 1); epc[p]++;
            fence_after();
            const int rowg = prevRow + (wid & 3) * 32 + lid;
#pragma unroll
            for (int q = 0; q < 8; q++) {
                uint32_t d[32];
                ldtm32(d, tmem + p * 256 + q * 32);
                wait_ld();
                const int col0 = q * 32;
                float* dst = (col0 < 128 ? EL + (size_t)rowg * DDIM + col0
                                         : ER + (size_t)rowg * DDIM + (col0 - 128));
#pragma unroll
                for (int u = 0; u < 8; u++)
                    *(float4*)(dst + u * 4) =
                        make_float4(__uint_as_float(d[4*u+0]), __uint_as_float(d[4*u+1]),
                                    __uint_as_float(d[4*u+2]), __uint_as_float(d[4*u+3]));
            }
            fence_before();
            mbar_arrive(sb + SM_EPID(p));
        }
        prevRow = tileRow; tl++;
    }

    if (wid >= 9 && wid <= 12 && tl >= 1) {
        const int p = (tl - 1) & 1;
        mbar_wait(sb + SM_EPI(p), epc[p] & 1); epc[p]++;
        fence_after();
        const int rowg = prevRow + (wid & 3) * 32 + lid;
#pragma unroll
        for (int q = 0; q < 8; q++) {
            uint32_t d[32];
            ldtm32(d, tmem + p * 256 + q * 32);
            wait_ld();
            const int col0 = q * 32;
            float* dst = (col0 < 128 ? EL + (size_t)rowg * DDIM + col0
                                     : ER + (size_t)rowg * DDIM + (col0 - 128));
#pragma unroll
            for (int u = 0; u < 8; u++)
                *(float4*)(dst + u * 4) =
                    make_float4(__uint_as_float(d[4*u+0]), __uint_as_float(d[4*u+1]),
                                __uint_as_float(d[4*u+2]), __uint_as_float(d[4*u+3]));
        }
        fence_before();
    }
    __syncthreads();
    if (wid == 0) tmem_dealloc(tmem, 512);
#else
    (void)emb; (void)W; (void)EL; (void)ER; (void)numTiles;
#endif
}

// ---------------------------------------------------------------------------
// Fused levels 1+2 (gather): producers warps 0-8 (288, 2-deep pipelined,
// ids register-cached per tile); epi warps 9-12; MMA warp 13.
// ---------------------------------------------------------------------------
__global__ __launch_bounds__(NT_PF, 1)
void fused12_tc(const int* __restrict__ ids,
                const float* __restrict__ EL, const float* __restrict__ ER,
                const float* __restrict__ W, const float* __restrict__ bias, int numTiles)
{
#if HAS_TCGEN05
    extern __shared__ char dsm[];
    const uint32_t sb = (smem_u32(dsm) + 1023) & ~1023u;
    const int tid = threadIdx.x, wid = tid >> 5, lid = tid & 31;
    char* arena = (char*)g_tree;

    if (tid == 0) {
#pragma unroll
        for (int s = 0; s < NSTAGE; s++) { mbar_init(SM_FULL(s) + sb, NPROD); mbar_init(SM_EMPTY(s) + sb, 1); }
#pragma unroll
        for (int p = 0; p < 2; p++) { mbar_init(SM_EPI(p) + sb, 1); mbar_init(SM_EPID(p) + sb, 128); }
    }
    if (tid < 128) sts_b32(sb + SM_BIAS + tid * 4, __float_as_uint(bias[tid]));

    if (tid < 256) {
        const int n = tid >> 1, h2 = tid & 1;
#pragma unroll
        for (int g = 0; g < 16; g++) {
            int k0 = h2 * 128 + g * 8;
            float4 v0 = *(const float4*)(W + (size_t)n * KDIM + k0);
            float4 v1 = *(const float4*)(W + (size_t)n * KDIM + k0 + 4);
            uint4 h, l; split8(v0, v1, h, l);
            uint32_t off = (k0 >> 6) * 16384 + swz(n * 128 + (k0 & 63) * 2);
            sts128(sb + SM_B + off, h.x, h.y, h.z, h.w);
            sts128(sb + SM_BLO + off, l.x, l.y, l.z, l.w);
        }
    }
    fence_proxy_async_s();
    __syncthreads();
    if (wid == 0) { tmem_alloc(sb + SM_TMEMP, 256); tmem_relinquish(); }
    __syncthreads();
    const uint32_t tmem = (uint32_t)lds_s32(sb + SM_TMEMP);

    const bool mmaLead = (wid == 13) && elect_one();
    int uc[NSTAGE] = {0, 0, 0}, fc[NSTAGE] = {0, 0, 0}, tp[2] = {0, 0}, epc[2] = {0, 0};
    int tl = 0, prevTile = 0;

    for (int tile = blockIdx.x; tile < numTiles; tile += gridDim.x) {
        const int tileRow = tile * TILE_M;
        if (tid < NPROD) {
            // ---- register-cache this thread's id pairs (<=4 rows x 2 sides) ----
            int2 idc[4][2];
#pragma unroll
            for (int k = 0; k < 4; k++) {
                const int ii = tid + k * NPROD;
                if (ii < 1024) {
                    const int r = tileRow + (ii >> 3);
                    idc[k][0] = *(const int2*)(ids + 4 * r);
                    idc[k][1] = *(const int2*)(ids + 4 * r + 2);
                }
            }
#pragma unroll
            for (int c = 0; c < 4; c++) {
                const int s = (tl * 4 + c) % NSTAGE;
                const uint32_t hiB = sb + SM_A + s * 32768, loB = hiB + 16384;
                const int ch = c >> 1, sub0 = (c & 1) * 64;

                // ---- 2-deep pipelined gather using cached ids ----
                int i0 = tid;
                int2 id0 = idc[0][ch];
                const float* pl0 = EL + (size_t)id0.x * DDIM + sub0 + (i0 & 7) * 8;
                const float* pr0 = ER + (size_t)id0.y * DDIM + sub0 + (i0 & 7) * 8;
                float4 l0 = *(const float4*)pl0,       l1 = *(const float4*)(pl0 + 4);
                float4 r0 = *(const float4*)pr0,       r1 = *(const float4*)(pr0 + 4);
                int i1 = i0 + NPROD, k1 = 1;

                if (uc[s] > 0) mbar_wait(sb + SM_EMPTY(s), (uc[s] - 1) & 1);
                uc[s]++;

                while (true) {
                    float4 nl0, nl1, nr0, nr1;
                    if (i1 < 1024) {
                        const int2 id1 = idc[k1][ch];
                        const float* pl1 = EL + (size_t)id1.x * DDIM + sub0 + (i1 & 7) * 8;
                        const float* pr1 = ER + (size_t)id1.y * DDIM + sub0 + (i1 & 7) * 8;
                        nl0 = *(const float4*)pl1; nl1 = *(const float4*)(pl1 + 4);
                        nr0 = *(const float4*)pr1; nr1 = *(const float4*)(pr1 + 4);
                    }
                    // process i0
                    {
                        const int sub = sub0 + (i0 & 7) * 8;
                        float4 b0 = lds_f32x4(sb + SM_BIAS + sub * 4);
                        float4 b1 = lds_f32x4(sb + SM_BIAS + (sub + 4) * 4);
                        float4 v0, v1;
                        v0.x = l0.x + r0.x + b0.x; v0.y = l0.y + r0.y + b0.y;
                        v0.z = l0.z + r0.z + b0.z; v0.w = l0.w + r0.w + b0.w;
                        v1.x = l1.x + r1.x + b1.x; v1.y = l1.y + r1.y + b1.y;
                        v1.z = l1.z + r1.z + b1.z; v1.w = l1.w + r1.w + b1.w;
                        uint4 h, l; split8(v0, v1, h, l);
                        const uint32_t off = swz((i0 >> 3) * 128 + (i0 & 7) * 16);
                        sts128(hiB + off, h.x, h.y, h.z, h.w);
                        sts128(loB + off, l.x, l.y, l.z, l.w);
                    }
                    if (i1 >= 1024) break;
                    i0 = i1; l0 = nl0; l1 = nl1; r0 = nr0; r1 = nr1;
                    i1 += NPROD; k1++;
                }
                fence_proxy_async_s();
                mbar_arrive(sb + SM_FULL(s));
            }
        } else if (mmaLead) {
            const int p = tl & 1;
            if (tp[p] > 0) mbar_wait(sb + SM_EPID(p), (tp[p] - 1) & 1);
            tp[p]++;
            const uint32_t dA = tmem + p * 128;
#pragma unroll
            for (int c = 0; c < 4; c++) {
                const int s = (tl * 4 + c) % NSTAGE;
                mbar_wait(sb + SM_FULL(s), fc[s] & 1); fc[s]++;
                mma_chunk(dA, sb, s, c, c == 0);
                mma_commit(sb + SM_EMPTY(s));
            }
            mma_commit(sb + SM_EPI(p));
        } else if (wid >= 9 && wid <= 12 && tl >= 1) {
            const int p = (tl - 1) & 1;
            mbar_wait(sb + SM_EPI(p), epc[p] & 1); epc[p]++;
            fence_after();
            epi_store_chunked(sb, tmem, p, prevTile, arena, (wid & 3) * 32 + lid);
            fence_before();
            fence_proxy_async_g();
            mbar_arrive(sb + SM_EPID(p));
        }
        prevTile = tile; tl++;
    }

    if (wid >= 9 && wid <= 12 && tl >= 1) {
        const int p = (tl - 1) & 1;
        mbar_wait(sb + SM_EPI(p), epc[p] & 1); epc[p]++;
        fence_after();
        epi_store_chunked(sb, tmem, p, prevTile, arena, (wid & 3) * 32 + lid);
        fence_before();
        fence_proxy_async_g();
    }
    __syncthreads();
    if (wid == 0) tmem_dealloc(tmem, 256);
#else
    (void)ids; (void)EL; (void)ER; (void)W; (void)bias; (void)numTiles;
#endif
}

// ---------------------------------------------------------------------------
// Tree kernel (R12): 128 CTAs local cascade; gemms 7-10 direct-SMEM A;
// small-V epilogues skip invalid warps.
// ---------------------------------------------------------------------------
__global__ __launch_bounds__(NT_TREE, 1)
void tree2_tc(const float* __restrict__ W, const float* __restrict__ bias,
              float* __restrict__ out)
{
#if HAS_TCGEN05
    extern __shared__ char dsm[];
    const uint32_t sb = (smem_u32(dsm) + 1023) & ~1023u;
    const int tid = threadIdx.x, wid = tid >> 5, lid = tid & 31;
    const int bid = blockIdx.x;
    char* arena = (char*)g_tree;
    char* S    = arena + SCR_BASE + (size_t)bid * SCR_STRIDE;
    char* FIN  = arena + FIN_BASE;
    char* FIN2 = arena + FIN2_BASE;

    if (tid == 0) {
#pragma unroll
        for (int s = 0; s < NSTAGE; s++) { mbar_init(SM_FULL(s) + sb, 1); mbar_init(SM_EMPTY(s) + sb, 1); }
#pragma unroll
        for (int p = 0; p < 2; p++) { mbar_init(SM_EPI(p) + sb, 1); mbar_init(SM_EPID(p) + sb, 128); }
    }
    if (tid < 128) sts_b32(sb + SM_BIAS + tid * 4, __float_as_uint(bias[tid]));

    {   // B = W chunks
        const int n = tid >> 1, h2 = tid & 1;
#pragma unroll
        for (int g = 0; g < 16; g++) {
            int k0 = h2 * 128 + g * 8;
            float4 v0 = *(const float4*)(W + (size_t)n * KDIM + k0);
            float4 v1 = *(const float4*)(W + (size_t)n * KDIM + k0 + 4);
            uint4 h, l; split8(v0, v1, h, l);
            uint32_t off = (k0 >> 6) * 16384 + swz(n * 128 + (k0 & 63) * 2);
            sts128(sb + SM_B + off, h.x, h.y, h.z, h.w);
            sts128(sb + SM_BLO + off, l.x, l.y, l.z, l.w);
        }
    }
    fence_proxy_async_s();
    __syncthreads();
    if (wid == 0) { tmem_alloc(sb + SM_TMEMP, 256); tmem_relinquish(); }
    __syncthreads();
    const uint32_t tmem = (uint32_t)lds_s32(sb + SM_TMEMP);

    const int nG = 11 + (bid < 4 ? 1 : 0) + (bid < 2 ? 1 : 0);

    if (wid == 7 && elect_one()) {
        int kChunk = 0;
        int issued[NSTAGE] = {0, 0, 0}, fcons[NSTAGE] = {0, 0, 0};
        int epidW[2] = {0, 0};
        int epiSeen = -1;
        auto waitEpi = [&](int e) {
            while (epiSeen < e) {
                epiSeen++;
                const int pp = epiSeen & 1;
                mbar_wait(sb + SM_EPID(pp), epidW[pp] & 1);
                epidW[pp]++;
            }
        };
        auto issueChunk = [&](int k, const char* src, uint32_t half, int c) {
            const int s = k % NSTAGE;
            if (issued[s] > 0) mbar_wait(sb + SM_EMPTY(s), (issued[s] - 1) & 1);
            issued[s]++;
            mbar_expect_tx(sb + SM_FULL(s), 2 * half);
            bulk_g2s(sb + SM_A + s * 32768,         src + (size_t)c * 2 * half,        half, sb + SM_FULL(s));
            bulk_g2s(sb + SM_A + s * 32768 + 16384, src + (size_t)c * 2 * half + half, half, sb + SM_FULL(s));
        };

        for (int g = 0; g < nG; g++) {
            if (g == 2 || g == 3) waitEpi(g - 2);
            else if (g == 4) waitEpi(2);
            else if (g == 5) waitEpi(3);
            else if (g == 6) waitEpi(5);
            else if (g >= 7) waitEpi(g - 1);
            if (g == 11) { while (ld_acq(&g_flags[0]) < 16384) nsleep(); }
            if (g == 12) { while (ld_acq(&g_flags[1]) < 512)   nsleep(); }

            const int p = g & 1;
            const uint32_t dA = tmem + p * 128;

            if (g >= 7 && g <= 10) {
                const uint32_t half = (g == 7) ? 8192u : (g == 8) ? 4096u : (g == 9) ? 2048u : 1024u;
#pragma unroll
                for (int c = 0; c < 4; c++)
                    mma_chunk_direct(dA, sb, half, c, c == 0);
            } else {
                const char* src; uint32_t half = 16384;
                if (g < 4)       src = arena + (size_t)(4 * bid + g) * BLKB;
                else if (g == 4) src = S;
                else if (g == 5) src = S + BLKB;
                else if (g == 6) src = S + A5OFF;
                else if (g == 11) src = FIN + (size_t)bid * BLKB;
                else              src = FIN2 + (size_t)bid * BLKB;

                issueChunk(kChunk + 0, src, half, 0);
                issueChunk(kChunk + 1, src, half, 1);
                issueChunk(kChunk + 2, src, half, 2);
                { const int s = kChunk % NSTAGE;
                  mbar_wait(sb + SM_FULL(s), fcons[s] & 1); fcons[s]++;
                  mma_chunk(dA, sb, s, 0, true);
                  mma_commit(sb + SM_EMPTY(s)); }
                issueChunk(kChunk + 3, src, half, 3);
#pragma unroll
                for (int c = 1; c < 4; c++) {
                    const int s = (kChunk + c) % NSTAGE;
                    mbar_wait(sb + SM_FULL(s), fcons[s] & 1); fcons[s]++;
                    mma_chunk(dA, sb, s, c, false);
                    mma_commit(sb + SM_EMPTY(s));
                }
                kChunk += 4;
            }
            mma_commit(sb + SM_EPI(p));
        }
    } else if (wid < 4) {
        int epc[2] = {0, 0};
        const int q = wid * 32 + lid;
        for (int e = 0; e < nG; e++) {
            const int p = e & 1;
            mbar_wait(sb + SM_EPI(p), epc[p] & 1); epc[p]++;
            fence_after();
            if (e == 12) {
                float* op = out + (size_t)(128 * bid + q) * DDIM;
#pragma unroll
                for (int qq = 0; qq < 4; qq++) {
                    uint32_t d[32];
                    ldtm32(d, tmem + p * 128 + qq * 32);
                    wait_ld();
#pragma unroll
                    for (int u = 0; u < 8; u++) {
                        float4 bv = lds_f32x4(sb + SM_BIAS + (qq * 32 + u * 4) * 4);
                        *(float4*)(op + qq * 32 + u * 4) =
                            make_float4(__uint_as_float(d[4*u+0]) + bv.x, __uint_as_float(d[4*u+1]) + bv.y,
                                        __uint_as_float(d[4*u+2]) + bv.z, __uint_as_float(d[4*u+3]) + bv.w);
                    }
                }
                fence_before();
            } else if (e >= 6 && e <= 9) {
                const uint32_t dArB = (e == 6) ? 8192u : (e == 7) ? 4096u : (e == 8) ? 2048u : 1024u;
                const int V = (e == 6) ? 128 : (e == 7) ? 64 : (e == 8) ? 32 : 16;
                epi_store2_smem(sb, tmem, p, V, sb + SM_A, dArB, q);
                fence_before();
                fence_proxy_async_s();
            } else {
                int V, ilBase; char* dst; uint32_t dArB = 16384;
                if (e < 6)       { V = 128; dst = S + (size_t)(e >> 1) * BLKB; ilBase = 64 * (e & 1); }
                else if (e == 10){ V = 8;   dst = FIN + (size_t)(bid >> 5) * BLKB; ilBase = 4 * (bid & 31); }
                else             { V = 128; dst = FIN2 + (size_t)(bid >> 1) * BLKB; ilBase = 64 * (bid & 1); }
                epi_store2(sb, tmem, p, V, dst, dArB, ilBase, q);
                fence_before();
                fence_proxy_async_g();
                if (e == 10) red_rel_add1(&g_flags[0]);
                if (e == 11) red_rel_add1(&g_flags[1]);
            }
            mbar_arrive(sb + SM_EPID(p));
        }
    }
    __syncthreads();
    if (wid == 0) tmem_dealloc(tmem, 256);
#else
    (void)W; (void)bias; (void)out;
#endif
}

// ---------------------------------------------------------------------------
extern "C" void kernel_launch(void* const* d_in, const int* in_sizes, int n_in,
                              void* d_out, int out_size)
{
    (void)in_sizes; (void)n_in; (void)out_size;
    const int*   ids  = (const int*)d_in[0];
    const float* emb  = (const float*)d_in[1];
    const float* W    = (const float*)d_in[2];
    const float* bias = (const float*)d_in[3];
    float* out = (float*)d_out;

    static bool attr_set = false;
    if (!attr_set) {
        cudaFuncSetAttribute(precompute_tc, cudaFuncAttributeMaxDynamicSharedMemorySize, DYN_SMEM);
        cudaFuncSetAttribute(fused12_tc,    cudaFuncAttributeMaxDynamicSharedMemorySize, DYN_SMEM);
        cudaFuncSetAttribute(tree2_tc,      cudaFuncAttributeMaxDynamicSharedMemorySize, DYN_SMEM);
        attr_set = true;
    }

    float *elp, *erp;
    cudaGetSymbolAddress((void**)&elp, g_EL);
    cudaGetSymbolAddress((void**)&erp, g_ER);

    clear_flags_k<<<4, 256>>>();
    precompute_tc<<<148, NT_PF, DYN_SMEM>>>(emb, W, elp, erp, VOCABPAD / TILE_M);
    fused12_tc<<<148, NT_PF, DYN_SMEM>>>(ids, elp, erp, W, bias, 1024);
    tree2_tc<<<128, NT_TREE, DYN_SMEM>>>(W, bias, out);
}